// round 6
// baseline (speedup 1.0000x reference)
#include <cuda_runtime.h>
#include <cuda_bf16.h>
#include <math.h>
#include <stdint.h>

// ---------------- problem constants ----------------
constexpr int kB = 2;
constexpr int kT = 16;
constexpr int kN = 1024;
constexpr int kC = 2;
constexpr int kCtok = 256;
constexpr int kQ = 320;
constexpr int kI = 512;
constexpr int kCD = 1024;
constexpr int kFF = 1280;
constexpr long kHS = (long)kB * kT * kN * kQ;
constexpr long kTOK = (long)kB * kT * kN;        // 32768

// ---------------- fp32 scratch ----------------
static __device__ float g_hs[kHS];
static __device__ float g_v[(long)kB * kC * kCtok * kI];
static __device__ float g_scores[kTOK * kI];
static __device__ float g_akv[kTOK * kI];
static __device__ float g_vdmax[(long)kB * kCtok * kI];
static __device__ float g_vtok[(long)kB * kN * kI];
static __device__ float g_aq[kTOK * kN];
static __device__ float g_p[kTOK * 2 * kFF];

// ---------------- bf16 scratch ----------------
static __device__ __nv_bfloat16 b_poset[kHS];
static __device__ __nv_bfloat16 b_ctxperm[(long)kB * 512 * kCD];
static __device__ __nv_bfloat16 b_ctx[(long)kB * kC * kCtok * kCD];
static __device__ __nv_bfloat16 b_WkT[(long)2 * kI * kCD];
static __device__ __nv_bfloat16 b_WvT[(long)2 * kI * kCD];
static __device__ __nv_bfloat16 b_WaT[(long)2 * kI * kQ];
static __device__ __nv_bfloat16 b_WqT[(long)2 * kI * kQ];
static __device__ __nv_bfloat16 b_WoT[(long)2 * kQ * kI];
static __device__ __nv_bfloat16 b_ffw1T[(long)2 * kFF * kQ];
static __device__ __nv_bfloat16 b_ffw2T[(long)kQ * kFF];
static __device__ __nv_bfloat16 b_kP[(long)kB * 512 * kI];
static __device__ __nv_bfloat16 b_vT[(long)kB * kC * kI * kCtok];
static __device__ __nv_bfloat16 b_atok[kTOK * kI];
static __device__ __nv_bfloat16 b_scores[kTOK * kI];
static __device__ __nv_bfloat16 b_akvT[kTOK * kI];
static __device__ __nv_bfloat16 b_q[kTOK * kI];
static __device__ __nv_bfloat16 b_aq[kTOK * kN];
static __device__ __nv_bfloat16 b_x[kTOK * kI];
static __device__ __nv_bfloat16 b_nh[kHS];
static __device__ __nv_bfloat16 b_gg[kTOK * kFF];

// ---------------- PTX helpers ----------------
__device__ __forceinline__ uint32_t smem_u32(const void* p) {
    return (uint32_t)__cvta_generic_to_shared(p);
}
__device__ __forceinline__ void cp16(uint32_t dst, const void* src, int src_bytes) {
    asm volatile("cp.async.cg.shared.global [%0], [%1], 16, %2;\n"
                 :: "r"(dst), "l"(src), "r"(src_bytes));
}
__device__ __forceinline__ void cp_commit() { asm volatile("cp.async.commit_group;\n"); }
template<int W> __device__ __forceinline__ void cp_wait() {
    asm volatile("cp.async.wait_group %0;\n" :: "n"(W));
}
__device__ __forceinline__ void mma16(float* d, const uint32_t* a, const uint32_t* b) {
    asm volatile(
        "mma.sync.aligned.m16n8k16.row.col.f32.bf16.bf16.f32 "
        "{%0,%1,%2,%3},{%4,%5,%6,%7},{%8,%9},{%0,%1,%2,%3};"
        : "+f"(d[0]), "+f"(d[1]), "+f"(d[2]), "+f"(d[3])
        : "r"(a[0]), "r"(a[1]), "r"(a[2]), "r"(a[3]), "r"(b[0]), "r"(b[1]));
}

// ---------------- bf16 NT tensor-core GEMM (R3 core + fused epilogues) ----------------
// C(MxN) = alpha * A(MxK,bf16,row) * B(NxK,bf16,row)^T + epilogues.
// flags: 1 += C ; 2 max C ; 4 += bias[col] ; 8 write bf16 natural Cb ;
//        16 write bf16 transposed Cb ; 32 suppress fp32 write ;
//        64  += aux[row*ldaux + col]                 (query_bias)
//        128 += aux[row*ldaux + (col&255)]           (agent_bias)
//        256 += aux[((z>>4)*1024 + row)*512 + col]   (v_tok broadcast)
// Requires M%128==0, K%32==0, lda/ldb %8==0. N guarded.
constexpr int SSTR = 40;   // bf16 smem row stride (80B, conflict-free)

__global__ __launch_bounds__(256, 2)
void bgemm_k(const __nv_bfloat16* __restrict__ A, const __nv_bfloat16* __restrict__ Bm,
             const float* __restrict__ bias, const float* __restrict__ aux,
             float* __restrict__ C, __nv_bfloat16* __restrict__ Cb,
             int M, int N, int K, int lda, int ldb, int ldc, int ldcb, int ldaux,
             long strA, long strB, long strC, long strCb,
             int bDiv, float alpha, int flags)
{
    __shared__ __align__(16) __nv_bfloat16 sA[2][128 * SSTR];
    __shared__ __align__(16) __nv_bfloat16 sB[2][128 * SSTR];

    const int z = blockIdx.z;
    const __nv_bfloat16* Ap = A + (size_t)z * strA;
    const __nv_bfloat16* Bp = Bm + (size_t)(z / bDiv) * strB;
    float* Cp = C + (size_t)z * strC;
    __nv_bfloat16* Cbp = Cb + (size_t)z * strCb;
    const int m0 = blockIdx.y * 128, n0 = blockIdx.x * 128;
    const int tid = threadIdx.x;
    const int lane = tid & 31, warp = tid >> 5;
    const int wm = warp & 1, wn = warp >> 1;      // 2x4 warps; warp tile 64x32
    const int gid = lane >> 2, tig = lane & 3;

    float acc[4][4][4];
    #pragma unroll
    for (int i = 0; i < 4; i++)
        #pragma unroll
        for (int j = 0; j < 4; j++)
            #pragma unroll
            for (int r = 0; r < 4; r++) acc[i][j][r] = 0.f;

    const int kTiles = K >> 5;

    auto load_tile = [&](int buf, int kt) {
        const int k0 = kt << 5;
        #pragma unroll
        for (int j = 0; j < 2; j++) {
            int i = tid + 256 * j;
            int r = i >> 2, c = i & 3;
            cp16(smem_u32(&sA[buf][r * SSTR + c * 8]),
                 Ap + (size_t)(m0 + r) * lda + k0 + c * 8, 16);
        }
        #pragma unroll
        for (int j = 0; j < 2; j++) {
            int i = tid + 256 * j;
            int r = i >> 2, c = i & 3;
            int gn = n0 + r;
            cp16(smem_u32(&sB[buf][r * SSTR + c * 8]),
                 Bp + (size_t)gn * ldb + k0 + c * 8, gn < N ? 16 : 0);
        }
        cp_commit();
    };

    auto compute_tile = [&](int buf) {
        #pragma unroll
        for (int s = 0; s < 2; s++) {
            const int kk = s * 16;
            uint32_t af[4][4], bf[4][2];
            #pragma unroll
            for (int mt = 0; mt < 4; mt++) {
                int rm = wm * 64 + mt * 16;
                const __nv_bfloat16* base = &sA[buf][(rm + gid) * SSTR + kk + 2 * tig];
                af[mt][0] = *(const uint32_t*)(base);
                af[mt][1] = *(const uint32_t*)(base + 8 * SSTR);
                af[mt][2] = *(const uint32_t*)(base + 8);
                af[mt][3] = *(const uint32_t*)(base + 8 * SSTR + 8);
            }
            #pragma unroll
            for (int nt = 0; nt < 4; nt++) {
                int cb = wn * 32 + nt * 8 + gid;
                const __nv_bfloat16* base = &sB[buf][cb * SSTR + kk + 2 * tig];
                bf[nt][0] = *(const uint32_t*)(base);
                bf[nt][1] = *(const uint32_t*)(base + 8);
            }
            #pragma unroll
            for (int mt = 0; mt < 4; mt++)
                #pragma unroll
                for (int nt = 0; nt < 4; nt++)
                    mma16(acc[mt][nt], af[mt], bf[nt]);
        }
    };

    load_tile(0, 0);
    for (int kt = 0; kt < kTiles; kt++) {
        if (kt + 1 < kTiles) {
            load_tile((kt + 1) & 1, kt + 1);
            cp_wait<1>();
        } else {
            cp_wait<0>();
        }
        __syncthreads();
        compute_tile(kt & 1);
        __syncthreads();
    }

    // epilogue
    #pragma unroll
    for (int mt = 0; mt < 4; mt++) {
        #pragma unroll
        for (int nt = 0; nt < 4; nt++) {
            int row0 = m0 + wm * 64 + mt * 16 + gid;
            int col0 = n0 + wn * 32 + nt * 8 + tig * 2;
            #pragma unroll
            for (int r = 0; r < 4; r++) {
                int rr = row0 + (r >> 1) * 8;
                int cc = col0 + (r & 1);
                if (cc >= N) continue;
                float vv = alpha * acc[mt][nt][r];
                size_t off = (size_t)rr * ldc + cc;
                if (flags & 4)   vv += bias[cc];
                if (flags & 64)  vv += aux[(size_t)rr * ldaux + cc];
                if (flags & 128) vv += aux[(size_t)rr * ldaux + (cc & 255)];
                if (flags & 256) vv += aux[(((size_t)(z >> 4)) * 1024 + rr) * 512 + cc];
                if (flags & 1) vv += Cp[off];
                if (flags & 2) vv = fmaxf(vv, Cp[off]);
                if (!(flags & 32)) Cp[off] = vv;
                if (flags & 8)  Cbp[(size_t)rr * ldcb + cc] = __float2bfloat16(vv);
                if (flags & 16) Cbp[(size_t)cc * ldcb + rr] = __float2bfloat16(vv);
            }
        }
    }
}

static void gemm(const __nv_bfloat16* A, const __nv_bfloat16* B, const float* bias,
                 const float* aux, float* C, __nv_bfloat16* Cb,
                 int M, int N, int K, int lda, int ldb, int ldc, int ldcb, int ldaux,
                 long sA, long sB, long sC, long sCb, int bDiv, int batch,
                 float alpha, int flags)
{
    dim3 gr((N + 127) / 128, M / 128, batch);
    bgemm_k<<<gr, 256>>>(A, B, bias, aux, C, Cb, M, N, K,
                         lda, ldb, ldc, ldcb, ldaux,
                         sA, sB, sC, sCb, bDiv, alpha, flags);
}

// ---------------- LayerNorm (bf16 out) ----------------
__global__ void ln_k(const float* __restrict__ x, const float* __restrict__ w,
                     const float* __restrict__ b, __nv_bfloat16* __restrict__ y, int cols)
{
    int row = blockIdx.x;
    const float* xp = x + (size_t)row * cols;
    float s1 = 0.f, s2 = 0.f;
    for (int i = threadIdx.x; i < cols; i += blockDim.x) {
        float v = xp[i]; s1 += v; s2 += v * v;
    }
    __shared__ float r1[256], r2[256];
    r1[threadIdx.x] = s1; r2[threadIdx.x] = s2;
    __syncthreads();
    for (int s = 128; s > 0; s >>= 1) {
        if (threadIdx.x < s) { r1[threadIdx.x] += r1[threadIdx.x + s]; r2[threadIdx.x] += r2[threadIdx.x + s]; }
        __syncthreads();
    }
    float mean = r1[0] / cols;
    float var = r2[0] / cols - mean * mean;
    float rstd = rsqrtf(var + 1e-5f);
    __nv_bfloat16* yp = y + (size_t)row * cols;
    for (int i = threadIdx.x; i < cols; i += blockDim.x)
        yp[i] = __float2bfloat16((xp[i] - mean) * rstd * w[i] + b[i]);
}

// ---------------- softmax kv groups (bias pre-added in GEMM) ----------------
__global__ void softmax_kv_k(const float* __restrict__ s, __nv_bfloat16* __restrict__ ob)
{
    long grp = (long)blockIdx.x * 8 + (threadIdx.x >> 5);
    int lane = threadIdx.x & 31;
    const float* p = s + grp * 256;
    __nv_bfloat16* po = ob + grp * 256;
    float v[8];
    float mx = -1e30f;
    #pragma unroll
    for (int i = 0; i < 8; i++) { v[i] = p[lane + i * 32]; mx = fmaxf(mx, v[i]); }
    #pragma unroll
    for (int o = 16; o; o >>= 1) mx = fmaxf(mx, __shfl_xor_sync(0xffffffffu, mx, o));
    float sum = 0.f;
    #pragma unroll
    for (int i = 0; i < 8; i++) { v[i] = __expf(v[i] - mx); sum += v[i]; }
    #pragma unroll
    for (int o = 16; o; o >>= 1) sum += __shfl_xor_sync(0xffffffffu, sum, o);
    float inv = 1.f / sum;
    #pragma unroll
    for (int i = 0; i < 8; i++) po[lane + i * 32] = __float2bfloat16(v[i] * inv);
}

// ---------------- softmax query rows (1024 cols; bias pre-added in GEMM) ----------------
__global__ void softmax_aq_k(const float* __restrict__ s, __nv_bfloat16* __restrict__ ob)
{
    int gr = blockIdx.x;
    const float* p = s + (size_t)gr * 1024;
    __nv_bfloat16* po = ob + (size_t)gr * 1024;
    int tid = threadIdx.x;
    float v[4];
    float mx = -1e30f;
    #pragma unroll
    for (int k = 0; k < 4; k++) { v[k] = p[tid + k * 256]; mx = fmaxf(mx, v[k]); }
    __shared__ float red[256];
    red[tid] = mx; __syncthreads();
    for (int st = 128; st; st >>= 1) { if (tid < st) red[tid] = fmaxf(red[tid], red[tid + st]); __syncthreads(); }
    mx = red[0]; __syncthreads();
    float sum = 0.f;
    #pragma unroll
    for (int k = 0; k < 4; k++) { v[k] = __expf(v[k] - mx); sum += v[k]; }
    red[tid] = sum; __syncthreads();
    for (int st = 128; st; st >>= 1) { if (tid < st) red[tid] += red[tid + st]; __syncthreads(); }
    float inv = 1.f / red[0];
    #pragma unroll
    for (int k = 0; k < 4; k++) po[tid + k * 256] = __float2bfloat16(v[k] * inv);
}

// ---------------- pose transpose -> bf16 ----------------
__global__ void poset_k(const float* __restrict__ pose, __nv_bfloat16* __restrict__ out)
{
    long idx = (long)blockIdx.x * blockDim.x + threadIdx.x;
    if (idx >= kHS) return;
    int d = (int)(idx % kQ);
    long r = idx / kQ;
    int n = (int)(r % kN); r /= kN;
    int t = (int)(r % kT); int b = (int)(r / kT);
    int h = n >> 5, w = n & 31;
    out[idx] = __float2bfloat16(pose[(((((size_t)b * kQ + d) * kT + t) * 32 + h) * 32) + w]);
}

// ---------------- context permuted rows -> bf16 ----------------
__global__ void ctxperm_k(const float* __restrict__ ctx, __nv_bfloat16* __restrict__ out)
{
    long idx = (long)blockIdx.x * blockDim.x + threadIdx.x;
    if (idx >= (long)kB * 512 * kCD) return;
    int k = (int)(idx % kCD);
    long r0 = idx / kCD;
    int r = (int)(r0 % 512); int b = (int)(r0 / 512);
    int n = ((r & 255) << 1) | (r >> 8);
    out[idx] = __float2bfloat16(ctx[(((size_t)b * kC + (n >> 8)) * kCtok + (n & 255)) * kCD + k]);
}

// ---------------- plain fp32->bf16 convert ----------------
__global__ void conv_k(const float* __restrict__ s, __nv_bfloat16* __restrict__ d, long n)
{
    long idx = (long)blockIdx.x * blockDim.x + threadIdx.x;
    if (idx < n) d[idx] = __float2bfloat16(s[idx]);
}

// ---------------- transpose convert: dst[b][c][r] = src[b][r][c] ----------------
__global__ void tconv_k(const float* __restrict__ s, __nv_bfloat16* __restrict__ d,
                        int R, int Cc, int batch)
{
    long n = (long)R * Cc * batch;
    long idx = (long)blockIdx.x * blockDim.x + threadIdx.x;
    if (idx >= n) return;
    int r = (int)(idx % R);
    long q = idx / R;
    int c = (int)(q % Cc);
    int b = (int)(q / Cc);
    d[idx] = __float2bfloat16(s[((size_t)b * R + r) * Cc + c]);
}

// ---------------- depthwise 3x3 conv + frame max + bias ----------------
__global__ void dwconv_k(const float* __restrict__ v, const float* __restrict__ wgt,
                         const float* __restrict__ bias, float* __restrict__ out)
{
    int pix = blockIdx.x & 255;
    int b = blockIdx.x >> 8;
    int e = threadIdx.x;
    int h = pix >> 4, w = pix & 15;
    float wv[9];
    #pragma unroll
    for (int t9 = 0; t9 < 9; t9++) wv[t9] = wgt[e * 9 + t9];
    float best = -1e30f;
    #pragma unroll
    for (int c = 0; c < 2; c++) {
        float s = 0.f;
        #pragma unroll
        for (int dh = -1; dh <= 1; dh++)
            #pragma unroll
            for (int dw = -1; dw <= 1; dw++) {
                int hh = h + dh, ww = w + dw;
                if (hh < 0 || hh > 15 || ww < 0 || ww > 15) continue;
                s += v[((size_t)(b * kC + c) * kCtok + hh * 16 + ww) * kI + e] * wv[(dh + 1) * 3 + (dw + 1)];
            }
        best = fmaxf(best, s);
    }
    out[((size_t)b * kCtok + pix) * kI + e] = best + bias[e];
}

// ---------------- bilinear x2 upsample ----------------
__global__ void upsample_k(const float* __restrict__ vd, float* __restrict__ vtok)
{
    int opix = blockIdx.x & 1023;
    int b = blockIdx.x >> 10;
    int e = threadIdx.x;
    int y = opix >> 5, x = opix & 31;
    int py = y >> 1, px = x >> 1;
    int y0, y1, x0, x1; float wy0, wy1, wx0, wx1;
    if (y & 1) { y0 = py; y1 = min(py + 1, 15); wy0 = 0.75f; wy1 = 0.25f; }
    else       { y0 = max(py - 1, 0); y1 = py;  wy0 = 0.25f; wy1 = 0.75f; }
    if (x & 1) { x0 = px; x1 = min(px + 1, 15); wx0 = 0.75f; wx1 = 0.25f; }
    else       { x0 = max(px - 1, 0); x1 = px;  wx0 = 0.25f; wx1 = 0.75f; }
    const float* base = vd + (size_t)b * kCtok * kI;
    float r = wy0 * wx0 * base[(size_t)(y0 * 16 + x0) * kI + e]
            + wy0 * wx1 * base[(size_t)(y0 * 16 + x1) * kI + e]
            + wy1 * wx0 * base[(size_t)(y1 * 16 + x0) * kI + e]
            + wy1 * wx1 * base[(size_t)(y1 * 16 + x1) * kI + e];
    vtok[((size_t)b * kN + opix) * kI + e] = r;
}

// ---------------- GEGLU -> bf16 ----------------
__global__ void geglu_k(const float* __restrict__ p, __nv_bfloat16* __restrict__ gg)
{
    long idx = (long)blockIdx.x * blockDim.x + threadIdx.x;
    if (idx >= kTOK * kFF) return;
    long m = idx / kFF; int j = (int)(idx % kFF);
    float a = p[m * (2 * kFF) + j];
    float g = p[m * (2 * kFF) + kFF + j];
    gg[idx] = __float2bfloat16(a * 0.5f * g * (1.f + erff(g * 0.70710678118654752f)));
}

// ---------------- launch ----------------
extern "C" void kernel_launch(void* const* d_in, const int* in_sizes, int n_in,
                              void* d_out, int out_size)
{
    const float* hidden     = (const float*)d_in[0];
    const float* context    = (const float*)d_in[1];
    const float* pose       = (const float*)d_in[2];
    const float* Wq         = (const float*)d_in[3];
    const float* Wk         = (const float*)d_in[4];
    const float* Wv         = (const float*)d_in[5];
    const float* Wa         = (const float*)d_in[6];
    const float* agent_bias = (const float*)d_in[7];
    const float* query_bias = (const float*)d_in[8];
    const float* dwc_w      = (const float*)d_in[9];
    const float* dwc_b      = (const float*)d_in[10];
    const float* Wo         = (const float*)d_in[11];
    const float* norm_w     = (const float*)d_in[12];
    const float* norm_b     = (const float*)d_in[13];
    const float* ffln_w     = (const float*)d_in[14];
    const float* ffln_b     = (const float*)d_in[15];
    const float* ff_w1      = (const float*)d_in[16];
    const float* ff_b1      = (const float*)d_in[17];
    const float* ff_w2      = (const float*)d_in[18];
    const float* ff_b2      = (const float*)d_in[19];

    float *hs, *vP, *scoresP, *akvP, *vdP, *vtokP, *aqP, *pP;
    cudaGetSymbolAddress((void**)&hs, g_hs);
    cudaGetSymbolAddress((void**)&vP, g_v);
    cudaGetSymbolAddress((void**)&scoresP, g_scores);
    cudaGetSymbolAddress((void**)&akvP, g_akv);
    cudaGetSymbolAddress((void**)&vdP, g_vdmax);
    cudaGetSymbolAddress((void**)&vtokP, g_vtok);
    cudaGetSymbolAddress((void**)&aqP, g_aq);
    cudaGetSymbolAddress((void**)&pP, g_p);

    __nv_bfloat16 *posetB, *ctxpermB, *ctxB, *WkT, *WvT, *WaT, *WqT, *WoT, *fw1T, *fw2T,
                  *kPB, *vTB, *atokB, *scoresB, *akvTB, *qB, *aqB, *xB, *nhB, *ggB;
    cudaGetSymbolAddress((void**)&posetB, b_poset);
    cudaGetSymbolAddress((void**)&ctxpermB, b_ctxperm);
    cudaGetSymbolAddress((void**)&ctxB, b_ctx);
    cudaGetSymbolAddress((void**)&WkT, b_WkT);
    cudaGetSymbolAddress((void**)&WvT, b_WvT);
    cudaGetSymbolAddress((void**)&WaT, b_WaT);
    cudaGetSymbolAddress((void**)&WqT, b_WqT);
    cudaGetSymbolAddress((void**)&WoT, b_WoT);
    cudaGetSymbolAddress((void**)&fw1T, b_ffw1T);
    cudaGetSymbolAddress((void**)&fw2T, b_ffw2T);
    cudaGetSymbolAddress((void**)&kPB, b_kP);
    cudaGetSymbolAddress((void**)&vTB, b_vT);
    cudaGetSymbolAddress((void**)&atokB, b_atok);
    cudaGetSymbolAddress((void**)&scoresB, b_scores);
    cudaGetSymbolAddress((void**)&akvTB, b_akvT);
    cudaGetSymbolAddress((void**)&qB, b_q);
    cudaGetSymbolAddress((void**)&aqB, b_aq);
    cudaGetSymbolAddress((void**)&xB, b_x);
    cudaGetSymbolAddress((void**)&nhB, b_nh);
    cudaGetSymbolAddress((void**)&ggB, b_gg);

    const float SCALE = 0.125f;
    auto cdiv = [](long a, long b) { return (int)((a + b - 1) / b); };

    cudaMemcpyAsync(hs, hidden, sizeof(float) * kHS, cudaMemcpyDeviceToDevice, 0);
    poset_k<<<cdiv(kHS, 256), 256>>>(pose, posetB);
    ctxperm_k<<<cdiv((long)kB * 512 * kCD, 256), 256>>>(context, ctxpermB);
    conv_k<<<cdiv((long)kB * kC * kCtok * kCD, 256), 256>>>(context, ctxB, (long)kB * kC * kCtok * kCD);
    tconv_k<<<cdiv((long)2 * kCD * kI, 256), 256>>>(Wk, WkT, kCD, kI, 2);
    tconv_k<<<cdiv((long)2 * kCD * kI, 256), 256>>>(Wv, WvT, kCD, kI, 2);
    tconv_k<<<cdiv((long)2 * kQ * kI, 256), 256>>>(Wa, WaT, kQ, kI, 2);
    tconv_k<<<cdiv((long)2 * kQ * kI, 256), 256>>>(Wq, WqT, kQ, kI, 2);
    tconv_k<<<cdiv((long)2 * kI * kQ, 256), 256>>>(Wo, WoT, kI, kQ, 2);
    tconv_k<<<cdiv((long)kQ * 2 * kFF, 256), 256>>>(ff_w1, fw1T, kQ, 2 * kFF, 1);
    tconv_k<<<cdiv((long)kFF * kQ, 256), 256>>>(ff_w2, fw2T, kFF, kQ, 1);

    for (int blk = 0; blk < 2; blk++) {
        const __nv_bfloat16* WkT_b = WkT + (size_t)blk * kI * kCD;
        const __nv_bfloat16* WvT_b = WvT + (size_t)blk * kI * kCD;
        const __nv_bfloat16* WaT_b = WaT + (size_t)blk * kI * kQ;
        const __nv_bfloat16* WqT_b = WqT + (size_t)blk * kI * kQ;
        const __nv_bfloat16* WoT_b = WoT + (size_t)blk * kQ * kI;
        const float* ab_b = agent_bias + (size_t)blk * kN * kCtok;
        const float* qb_b = query_bias + (size_t)blk * kN * kN;
        const float* dw_b = dwc_w + (size_t)blk * kI * 9;
        const float* db_b = dwc_b + (size_t)blk * kI;

        // kP (bf16 natural): [b] 512x512, K=1024
        gemm(ctxpermB, WkT_b, nullptr, nullptr, nullptr, kPB,
             512, kI, kCD, kCD, kCD, 0, kI, 0,
             512L * kCD, 0, 0, 512L * kI, 1, kB, 1.f, 8 | 32);
        // v proj: fp32 natural (dwconv input) + bf16 transposed; [b,c] 256x512, K=1024
        gemm(ctxB, WvT_b, nullptr, nullptr, vP, vTB,
             kCtok, kI, kCD, kCD, kCD, kI, kCtok, 0,
             (long)kCtok * kCD, 0, (long)kCtok * kI, (long)kI * kCtok, 1, kB * kC, 1.f, 16);
        // a_tok (bf16 natural): 32768x512, K=320
        gemm(posetB, WaT_b, nullptr, nullptr, nullptr, atokB,
             (int)kTOK, kI, kQ, kQ, kQ, 0, kI, 0,
             0, 0, 0, 0, 1, 1, 1.f, 8 | 32);
        // scores = SCALE*atok@kP^T + agent_bias : per (b,t) 1024x512, K=512
        gemm(atokB, kPB, nullptr, ab_b, scoresP, nullptr,
             kN, 512, kI, kI, kI, 512, 0, kCtok,
             (long)kN * kI, 512L * kI, (long)kN * 512, 0, kT, kB * kT, SCALE, 128);
        softmax_kv_k<<<(int)(kTOK * 2 / 8), 256>>>(scoresP, scoresB);
        // agent_kv = max_c2(probs_c2 @ v_c2): per (b,t) 1024x512, K=256
        gemm(scoresB, vTB, nullptr, nullptr, akvP, nullptr,
             kN, kI, kCtok, 512, kCtok, kI, 0, 0,
             (long)kN * 512, (long)kC * kI * kCtok, (long)kN * kI, 0, kT, kB * kT, 1.f, 0);
        gemm(scoresB + 256, vTB + (size_t)kI * kCtok, nullptr, nullptr, akvP, akvTB,
             kN, kI, kCtok, 512, kCtok, kI, kN, 0,
             (long)kN * 512, (long)kC * kI * kCtok, (long)kN * kI, (long)kI * kN, kT, kB * kT,
             1.f, 2 | 16 | 32);
        // dwconv + upsample
        dwconv_k<<<kB * kCtok, kI>>>(vP, dw_b, db_b, vdP);
        upsample_k<<<kB * kN, kI>>>(vdP, vtokP);
        // LN + q proj
        ln_k<<<(int)kTOK, 256>>>(hs, norm_w, norm_b, nhB, kQ);
        gemm(nhB, WqT_b, nullptr, nullptr, nullptr, qB,
             (int)kTOK, kI, kQ, kQ, kQ, 0, kI, 0,
             0, 0, 0, 0, 1, 1, 1.f, 8 | 32);
        // aq = SCALE*q@atok^T + query_bias : per (b,t) 1024x1024, K=512
        gemm(qB, atokB, nullptr, qb_b, aqP, nullptr,
             kN, kN, kI, kI, kI, kN, 0, kN,
             (long)kN * kI, (long)kN * kI, (long)kN * kN, 0, 1, kB * kT, SCALE, 64);
        softmax_aq_k<<<(int)kTOK, 256>>>(aqP, aqB);
        // x = aq@akv + v_tok -> bf16 : per (b,t) 1024x512, K=1024
        gemm(aqB, akvTB, nullptr, vtokP, nullptr, xB,
             kN, kI, kN, kN, kN, 0, kI, 0,
             (long)kN * kN, (long)kI * kN, 0, (long)kN * kI, 1, kB * kT,
             1.f, 256 | 8 | 32);
        // hs += x @ Wo : 32768x320, K=512
        gemm(xB, WoT_b, nullptr, nullptr, hs, nullptr,
             (int)kTOK, kQ, kI, kI, kI, kQ, 0, 0,
             0, 0, 0, 0, 1, 1, 1.f, 1);
    }

    // ---- FF ----
    ln_k<<<(int)kTOK, 256>>>(hs, ffln_w, ffln_b, nhB, kQ);
    gemm(nhB, fw1T, ff_b1, nullptr, pP, nullptr,
         (int)kTOK, 2 * kFF, kQ, kQ, kQ, 2 * kFF, 0, 0,
         0, 0, 0, 0, 1, 1, 1.f, 4);
    geglu_k<<<cdiv(kTOK * kFF, 256), 256>>>(pP, ggB);
    gemm(ggB, fw2T, ff_b2, nullptr, hs, nullptr,
         (int)kTOK, kQ, kFF, kFF, kFF, kQ, 0, 0,
         0, 0, 0, 0, 1, 1, 1.f, 1 | 4);

    cudaMemcpyAsync(d_out, hs, sizeof(float) * kHS, cudaMemcpyDeviceToDevice, 0);
}

// round 8
// speedup vs baseline: 1.2061x; 1.2061x over previous
#include <cuda_runtime.h>
#include <cuda_bf16.h>
#include <math.h>
#include <stdint.h>

// ---------------- problem constants ----------------
constexpr int kB = 2;
constexpr int kT = 16;
constexpr int kN = 1024;
constexpr int kC = 2;
constexpr int kCtok = 256;
constexpr int kQ = 320;
constexpr int kI = 512;
constexpr int kCD = 1024;
constexpr int kFF = 1280;
constexpr long kHS = (long)kB * kT * kN * kQ;
constexpr long kTOK = (long)kB * kT * kN;        // 32768

// ---------------- fp32 scratch ----------------
static __device__ float g_hs[kHS];
static __device__ float g_v[(long)kB * kC * kCtok * kI];
static __device__ float g_scores[kTOK * kI];
static __device__ float g_akv[kTOK * kI];
static __device__ float g_vdmax[(long)kB * kCtok * kI];
static __device__ float g_vtok[(long)kB * kN * kI];
static __device__ float g_aq[kTOK * kN];
static __device__ float g_x[kTOK * kI];
static __device__ float g_ffb1i[2 * kFF];

// ---------------- bf16 scratch ----------------
static __device__ __nv_bfloat16 b_poset[kHS];
static __device__ __nv_bfloat16 b_ctxperm[(long)kB * 512 * kCD];
static __device__ __nv_bfloat16 b_ctx[(long)kB * kC * kCtok * kCD];
static __device__ __nv_bfloat16 b_WkT[(long)2 * kI * kCD];
static __device__ __nv_bfloat16 b_WvT[(long)2 * kI * kCD];
static __device__ __nv_bfloat16 b_WaT[(long)2 * kI * kQ];
static __device__ __nv_bfloat16 b_WqT[(long)2 * kI * kQ];
static __device__ __nv_bfloat16 b_WoT[(long)2 * kQ * kI];
static __device__ __nv_bfloat16 b_ffw1T[(long)2 * kFF * kQ];   // interleaved a/g pairs
static __device__ __nv_bfloat16 b_ffw2T[(long)kQ * kFF];
static __device__ __nv_bfloat16 b_kP[(long)kB * 512 * kI];
static __device__ __nv_bfloat16 b_vT[(long)kB * kC * kI * kCtok];
static __device__ __nv_bfloat16 b_atok[kTOK * kI];
static __device__ __nv_bfloat16 b_scores[kTOK * kI];
static __device__ __nv_bfloat16 b_akvT[kTOK * kI];
static __device__ __nv_bfloat16 b_q[kTOK * kI];
static __device__ __nv_bfloat16 b_aq[kTOK * kN];
static __device__ __nv_bfloat16 b_x[kTOK * kI];
static __device__ __nv_bfloat16 b_nh[kHS];
static __device__ __nv_bfloat16 b_gg[kTOK * kFF];

// ---------------- PTX helpers ----------------
__device__ __forceinline__ uint32_t smem_u32(const void* p) {
    return (uint32_t)__cvta_generic_to_shared(p);
}
__device__ __forceinline__ void cp16(uint32_t dst, const void* src, int src_bytes) {
    asm volatile("cp.async.cg.shared.global [%0], [%1], 16, %2;\n"
                 :: "r"(dst), "l"(src), "r"(src_bytes));
}
__device__ __forceinline__ void cp_commit() { asm volatile("cp.async.commit_group;\n"); }
template<int W> __device__ __forceinline__ void cp_wait() {
    asm volatile("cp.async.wait_group %0;\n" :: "n"(W));
}
__device__ __forceinline__ void mma16(float* d, const uint32_t* a, const uint32_t* b) {
    asm volatile(
        "mma.sync.aligned.m16n8k16.row.col.f32.bf16.bf16.f32 "
        "{%0,%1,%2,%3},{%4,%5,%6,%7},{%8,%9},{%0,%1,%2,%3};"
        : "+f"(d[0]), "+f"(d[1]), "+f"(d[2]), "+f"(d[3])
        : "r"(a[0]), "r"(a[1]), "r"(a[2]), "r"(a[3]), "r"(b[0]), "r"(b[1]));
}

// ---------------- bf16 NT tensor-core GEMM (R3 core) ----------------
// C(MxN) = alpha * A(MxK,bf16,row) * B(NxK,bf16,row)^T + epilogues.
// flags: 1 += C ; 2 max C ; 4 += bias[col] ; 8 write bf16 natural Cb ;
//        16 write bf16 transposed Cb ; 32 suppress fp32 write ;
//        512 GEGLU pair epilogue: cols interleaved (even=a, odd=g),
//            writes bf16 a*gelu(g) to Cb at column col/2 (ldcb = N/2).
// Requires M%128==0, K%32==0, lda/ldb %8==0. N guarded (except flag 512: N%128==0).
constexpr int SSTR = 40;   // bf16 smem row stride (80B, conflict-free)

__global__ __launch_bounds__(256, 2)
void bgemm_k(const __nv_bfloat16* __restrict__ A, const __nv_bfloat16* __restrict__ Bm,
             const float* __restrict__ bias, float* __restrict__ C,
             __nv_bfloat16* __restrict__ Cb,
             int M, int N, int K, int lda, int ldb, int ldc, int ldcb,
             long strA, long strB, long strC, long strCb,
             int bDiv, float alpha, int flags)
{
    __shared__ __align__(16) __nv_bfloat16 sA[2][128 * SSTR];
    __shared__ __align__(16) __nv_bfloat16 sB[2][128 * SSTR];

    const int z = blockIdx.z;
    const __nv_bfloat16* Ap = A + (size_t)z * strA;
    const __nv_bfloat16* Bp = Bm + (size_t)(z / bDiv) * strB;
    float* Cp = C + (size_t)z * strC;
    __nv_bfloat16* Cbp = Cb + (size_t)z * strCb;
    const int m0 = blockIdx.y * 128, n0 = blockIdx.x * 128;
    const int tid = threadIdx.x;
    const int lane = tid & 31, warp = tid >> 5;
    const int wm = warp & 1, wn = warp >> 1;      // 2x4 warps; warp tile 64x32
    const int gid = lane >> 2, tig = lane & 3;

    float acc[4][4][4];
    #pragma unroll
    for (int i = 0; i < 4; i++)
        #pragma unroll
        for (int j = 0; j < 4; j++)
            #pragma unroll
            for (int r = 0; r < 4; r++) acc[i][j][r] = 0.f;

    const int kTiles = K >> 5;

    auto load_tile = [&](int buf, int kt) {
        const int k0 = kt << 5;
        #pragma unroll
        for (int j = 0; j < 2; j++) {
            int i = tid + 256 * j;
            int r = i >> 2, c = i & 3;
            cp16(smem_u32(&sA[buf][r * SSTR + c * 8]),
                 Ap + (size_t)(m0 + r) * lda + k0 + c * 8, 16);
        }
        #pragma unroll
        for (int j = 0; j < 2; j++) {
            int i = tid + 256 * j;
            int r = i >> 2, c = i & 3;
            int gn = n0 + r;
            cp16(smem_u32(&sB[buf][r * SSTR + c * 8]),
                 Bp + (size_t)gn * ldb + k0 + c * 8, gn < N ? 16 : 0);
        }
        cp_commit();
    };

    auto compute_tile = [&](int buf) {
        #pragma unroll
        for (int s = 0; s < 2; s++) {
            const int kk = s * 16;
            uint32_t af[4][4], bf[4][2];
            #pragma unroll
            for (int mt = 0; mt < 4; mt++) {
                int rm = wm * 64 + mt * 16;
                const __nv_bfloat16* base = &sA[buf][(rm + gid) * SSTR + kk + 2 * tig];
                af[mt][0] = *(const uint32_t*)(base);
                af[mt][1] = *(const uint32_t*)(base + 8 * SSTR);
                af[mt][2] = *(const uint32_t*)(base + 8);
                af[mt][3] = *(const uint32_t*)(base + 8 * SSTR + 8);
            }
            #pragma unroll
            for (int nt = 0; nt < 4; nt++) {
                int cb = wn * 32 + nt * 8 + gid;
                const __nv_bfloat16* base = &sB[buf][cb * SSTR + kk + 2 * tig];
                bf[nt][0] = *(const uint32_t*)(base);
                bf[nt][1] = *(const uint32_t*)(base + 8);
            }
            #pragma unroll
            for (int mt = 0; mt < 4; mt++)
                #pragma unroll
                for (int nt = 0; nt < 4; nt++)
                    mma16(acc[mt][nt], af[mt], bf[nt]);
        }
    };

    load_tile(0, 0);
    for (int kt = 0; kt < kTiles; kt++) {
        if (kt + 1 < kTiles) {
            load_tile((kt + 1) & 1, kt + 1);
            cp_wait<1>();
        } else {
            cp_wait<0>();
        }
        __syncthreads();
        compute_tile(kt & 1);
        __syncthreads();
    }

    // epilogue
    #pragma unroll
    for (int mt = 0; mt < 4; mt++) {
        #pragma unroll
        for (int nt = 0; nt < 4; nt++) {
            int row0 = m0 + wm * 64 + mt * 16 + gid;
            int col0 = n0 + wn * 32 + nt * 8 + tig * 2;
            if (flags & 512) {
                // interleaved GEGLU: (even,odd) = (a, g) for output column col0/2
                float ba = bias[col0], bg = bias[col0 + 1];
                #pragma unroll
                for (int h = 0; h < 2; h++) {
                    int rr = row0 + h * 8;
                    float a = alpha * acc[mt][nt][2 * h] + ba;
                    float g = alpha * acc[mt][nt][2 * h + 1] + bg;
                    float gg = a * 0.5f * g * (1.f + erff(g * 0.70710678118654752f));
                    Cbp[(size_t)rr * ldcb + (col0 >> 1)] = __float2bfloat16(gg);
                }
                continue;
            }
            #pragma unroll
            for (int r = 0; r < 4; r++) {
                int rr = row0 + (r >> 1) * 8;
                int cc = col0 + (r & 1);
                if (cc >= N) continue;
                float vv = alpha * acc[mt][nt][r];
                size_t off = (size_t)rr * ldc + cc;
                if (flags & 4) vv += bias[cc];
                if (flags & 1) vv += Cp[off];
                if (flags & 2) vv = fmaxf(vv, Cp[off]);
                if (!(flags & 32)) Cp[off] = vv;
                if (flags & 8)  Cbp[(size_t)rr * ldcb + cc] = __float2bfloat16(vv);
                if (flags & 16) Cbp[(size_t)cc * ldcb + rr] = __float2bfloat16(vv);
            }
        }
    }
}

static void gemm(const __nv_bfloat16* A, const __nv_bfloat16* B, const float* bias,
                 float* C, __nv_bfloat16* Cb,
                 int M, int N, int K, int lda, int ldb, int ldc, int ldcb,
                 long sA, long sB, long sC, long sCb, int bDiv, int batch,
                 float alpha, int flags)
{
    dim3 gr((N + 127) / 128, M / 128, batch);
    bgemm_k<<<gr, 256>>>(A, B, bias, C, Cb, M, N, K, lda, ldb, ldc, ldcb,
                         sA, sB, sC, sCb, bDiv, alpha, flags);
}

// ---------------- LayerNorm (bf16 out) ----------------
__global__ void ln_k(const float* __restrict__ x, const float* __restrict__ w,
                     const float* __restrict__ b, __nv_bfloat16* __restrict__ y, int cols)
{
    int row = blockIdx.x;
    const float* xp = x + (size_t)row * cols;
    float s1 = 0.f, s2 = 0.f;
    for (int i = threadIdx.x; i < cols; i += blockDim.x) {
        float v = xp[i]; s1 += v; s2 += v * v;
    }
    __shared__ float r1[256], r2[256];
    r1[threadIdx.x] = s1; r2[threadIdx.x] = s2;
    __syncthreads();
    for (int s = 128; s > 0; s >>= 1) {
        if (threadIdx.x < s) { r1[threadIdx.x] += r1[threadIdx.x + s]; r2[threadIdx.x] += r2[threadIdx.x + s]; }
        __syncthreads();
    }
    float mean = r1[0] / cols;
    float var = r2[0] / cols - mean * mean;
    float rstd = rsqrtf(var + 1e-5f);
    __nv_bfloat16* yp = y + (size_t)row * cols;
    for (int i = threadIdx.x; i < cols; i += blockDim.x)
        yp[i] = __float2bfloat16((xp[i] - mean) * rstd * w[i] + b[i]);
}

// ---------------- softmax kv groups (256 cols, + agent_bias[m,nc2]) -> bf16 ----------------
__global__ void softmax_kv_k(const float* __restrict__ s, const float* __restrict__ abias,
                             __nv_bfloat16* __restrict__ ob)
{
    int gr = blockIdx.x;
    int c2 = blockIdx.y;
    int m = gr & 1023;
    const float* p = s + (size_t)gr * 512 + c2 * 256;
    __nv_bfloat16* po = ob + (size_t)gr * 512 + c2 * 256;
    int tid = threadIdx.x;
    float v = p[tid] + abias[(size_t)m * 256 + tid];
    __shared__ float red[256];
    red[tid] = v; __syncthreads();
    for (int st = 128; st; st >>= 1) { if (tid < st) red[tid] = fmaxf(red[tid], red[tid + st]); __syncthreads(); }
    float mx = red[0]; __syncthreads();
    float e = __expf(v - mx);
    red[tid] = e; __syncthreads();
    for (int st = 128; st; st >>= 1) { if (tid < st) red[tid] += red[tid + st]; __syncthreads(); }
    po[tid] = __float2bfloat16(e / red[0]);
}

// ---------------- softmax query rows (1024 cols, + query_bias[n,m]) -> bf16 ----------------
__global__ void softmax_aq_k(const float* __restrict__ s, const float* __restrict__ qbias,
                             __nv_bfloat16* __restrict__ ob)
{
    int gr = blockIdx.x;
    int n = gr & 1023;
    const float* p = s + (size_t)gr * 1024;
    __nv_bfloat16* po = ob + (size_t)gr * 1024;
    const float* bp = qbias + (size_t)n * 1024;
    int tid = threadIdx.x;
    float v[4];
    float mx = -1e30f;
    #pragma unroll
    for (int k = 0; k < 4; k++) { v[k] = p[tid + k * 256] + bp[tid + k * 256]; mx = fmaxf(mx, v[k]); }
    __shared__ float red[256];
    red[tid] = mx; __syncthreads();
    for (int st = 128; st; st >>= 1) { if (tid < st) red[tid] = fmaxf(red[tid], red[tid + st]); __syncthreads(); }
    mx = red[0]; __syncthreads();
    float sum = 0.f;
    #pragma unroll
    for (int k = 0; k < 4; k++) { v[k] = __expf(v[k] - mx); sum += v[k]; }
    red[tid] = sum; __syncthreads();
    for (int st = 128; st; st >>= 1) { if (tid < st) red[tid] += red[tid + st]; __syncthreads(); }
    float inv = 1.f / red[0];
    #pragma unroll
    for (int k = 0; k < 4; k++) po[tid + k * 256] = __float2bfloat16(v[k] * inv);
}

// ---------------- pose transpose -> bf16 ----------------
__global__ void poset_k(const float* __restrict__ pose, __nv_bfloat16* __restrict__ out)
{
    long idx = (long)blockIdx.x * blockDim.x + threadIdx.x;
    if (idx >= kHS) return;
    int d = (int)(idx % kQ);
    long r = idx / kQ;
    int n = (int)(r % kN); r /= kN;
    int t = (int)(r % kT); int b = (int)(r / kT);
    int h = n >> 5, w = n & 31;
    out[idx] = __float2bfloat16(pose[(((((size_t)b * kQ + d) * kT + t) * 32 + h) * 32) + w]);
}

// ---------------- context permuted rows -> bf16 ----------------
__global__ void ctxperm_k(const float* __restrict__ ctx, __nv_bfloat16* __restrict__ out)
{
    long idx = (long)blockIdx.x * blockDim.x + threadIdx.x;
    if (idx >= (long)kB * 512 * kCD) return;
    int k = (int)(idx % kCD);
    long r0 = idx / kCD;
    int r = (int)(r0 % 512); int b = (int)(r0 / 512);
    int n = ((r & 255) << 1) | (r >> 8);
    out[idx] = __float2bfloat16(ctx[(((size_t)b * kC + (n >> 8)) * kCtok + (n & 255)) * kCD + k]);
}

// ---------------- plain fp32->bf16 convert ----------------
__global__ void conv_k(const float* __restrict__ s, __nv_bfloat16* __restrict__ d, long n)
{
    long idx = (long)blockIdx.x * blockDim.x + threadIdx.x;
    if (idx < n) d[idx] = __float2bfloat16(s[idx]);
}

// ---------------- transpose convert: dst[b][c][r] = src[b][r][c] ----------------
__global__ void tconv_k(const float* __restrict__ s, __nv_bfloat16* __restrict__ d,
                        int R, int Cc, int batch)
{
    long n = (long)R * Cc * batch;
    long idx = (long)blockIdx.x * blockDim.x + threadIdx.x;
    if (idx >= n) return;
    int r = (int)(idx % R);
    long q = idx / R;
    int c = (int)(q % Cc);
    int b = (int)(q / Cc);
    d[idx] = __float2bfloat16(s[((size_t)b * R + r) * Cc + c]);
}

// ---------------- FF1 weight transpose with a/g column interleave ----------------
// d[e][k] = ff_w1[k][orig(e)], orig(e) = (e odd) ? kFF + e/2 : e/2
__global__ void w1i_k(const float* __restrict__ s, __nv_bfloat16* __restrict__ d)
{
    long n = (long)2 * kFF * kQ;
    long idx = (long)blockIdx.x * blockDim.x + threadIdx.x;
    if (idx >= n) return;
    int k = (int)(idx % kQ);
    int e = (int)(idx / kQ);
    int oc = (e & 1) ? (kFF + (e >> 1)) : (e >> 1);
    d[idx] = __float2bfloat16(s[(size_t)k * (2 * kFF) + oc]);
}
__global__ void b1i_k(const float* __restrict__ s, float* __restrict__ d)
{
    int e = blockIdx.x * blockDim.x + threadIdx.x;
    if (e >= 2 * kFF) return;
    int oc = (e & 1) ? (kFF + (e >> 1)) : (e >> 1);
    d[e] = s[oc];
}

// ---------------- depthwise 3x3 conv + frame max + bias ----------------
__global__ void dwconv_k(const float* __restrict__ v, const float* __restrict__ wgt,
                         const float* __restrict__ bias, float* __restrict__ out)
{
    int pix = blockIdx.x & 255;
    int b = blockIdx.x >> 8;
    int e = threadIdx.x;
    int h = pix >> 4, w = pix & 15;
    float wv[9];
    #pragma unroll
    for (int t9 = 0; t9 < 9; t9++) wv[t9] = wgt[e * 9 + t9];
    float best = -1e30f;
    #pragma unroll
    for (int c = 0; c < 2; c++) {
        float s = 0.f;
        #pragma unroll
        for (int dh = -1; dh <= 1; dh++)
            #pragma unroll
            for (int dw = -1; dw <= 1; dw++) {
                int hh = h + dh, ww = w + dw;
                if (hh < 0 || hh > 15 || ww < 0 || ww > 15) continue;
                s += v[((size_t)(b * kC + c) * kCtok + hh * 16 + ww) * kI + e] * wv[(dh + 1) * 3 + (dw + 1)];
            }
        best = fmaxf(best, s);
    }
    out[((size_t)b * kCtok + pix) * kI + e] = best + bias[e];
}

// ---------------- bilinear x2 upsample ----------------
__global__ void upsample_k(const float* __restrict__ vd, float* __restrict__ vtok)
{
    int opix = blockIdx.x & 1023;
    int b = blockIdx.x >> 10;
    int e = threadIdx.x;
    int y = opix >> 5, x = opix & 31;
    int py = y >> 1, px = x >> 1;
    int y0, y1, x0, x1; float wy0, wy1, wx0, wx1;
    if (y & 1) { y0 = py; y1 = min(py + 1, 15); wy0 = 0.75f; wy1 = 0.25f; }
    else       { y0 = max(py - 1, 0); y1 = py;  wy0 = 0.25f; wy1 = 0.75f; }
    if (x & 1) { x0 = px; x1 = min(px + 1, 15); wx0 = 0.75f; wx1 = 0.25f; }
    else       { x0 = max(px - 1, 0); x1 = px;  wx0 = 0.25f; wx1 = 0.75f; }
    const float* base = vd + (size_t)b * kCtok * kI;
    float r = wy0 * wx0 * base[(size_t)(y0 * 16 + x0) * kI + e]
            + wy0 * wx1 * base[(size_t)(y0 * 16 + x1) * kI + e]
            + wy1 * wx0 * base[(size_t)(y1 * 16 + x0) * kI + e]
            + wy1 * wx1 * base[(size_t)(y1 * 16 + x1) * kI + e];
    vtok[((size_t)b * kN + opix) * kI + e] = r;
}

// ---------------- x = x + v_tok -> bf16 ----------------
__global__ void addvtok_k(const float* __restrict__ x, const float* __restrict__ vtok,
                          __nv_bfloat16* __restrict__ xb)
{
    long idx = (long)blockIdx.x * blockDim.x + threadIdx.x;
    if (idx >= kTOK * kI) return;
    int e = (int)(idx % kI);
    long r = idx / kI;
    int n = (int)(r % kN);
    int b = (int)(r / ((long)kN * kT));
    xb[idx] = __float2bfloat16(x[idx] + vtok[((size_t)b * kN + n) * kI + e]);
}

// ---------------- launch ----------------
extern "C" void kernel_launch(void* const* d_in, const int* in_sizes, int n_in,
                              void* d_out, int out_size)
{
    const float* hidden     = (const float*)d_in[0];
    const float* context    = (const float*)d_in[1];
    const float* pose       = (const float*)d_in[2];
    const float* Wq         = (const float*)d_in[3];
    const float* Wk         = (const float*)d_in[4];
    const float* Wv         = (const float*)d_in[5];
    const float* Wa         = (const float*)d_in[6];
    const float* agent_bias = (const float*)d_in[7];
    const float* query_bias = (const float*)d_in[8];
    const float* dwc_w      = (const float*)d_in[9];
    const float* dwc_b      = (const float*)d_in[10];
    const float* Wo         = (const float*)d_in[11];
    const float* norm_w     = (const float*)d_in[12];
    const float* norm_b     = (const float*)d_in[13];
    const float* ffln_w     = (const float*)d_in[14];
    const float* ffln_b     = (const float*)d_in[15];
    const float* ff_w1      = (const float*)d_in[16];
    const float* ff_b1      = (const float*)d_in[17];
    const float* ff_w2      = (const float*)d_in[18];
    const float* ff_b2      = (const float*)d_in[19];

    float *hs, *vP, *scoresP, *akvP, *vdP, *vtokP, *aqP, *xP, *ffb1iP;
    cudaGetSymbolAddress((void**)&hs, g_hs);
    cudaGetSymbolAddress((void**)&vP, g_v);
    cudaGetSymbolAddress((void**)&scoresP, g_scores);
    cudaGetSymbolAddress((void**)&akvP, g_akv);
    cudaGetSymbolAddress((void**)&vdP, g_vdmax);
    cudaGetSymbolAddress((void**)&vtokP, g_vtok);
    cudaGetSymbolAddress((void**)&aqP, g_aq);
    cudaGetSymbolAddress((void**)&xP, g_x);
    cudaGetSymbolAddress((void**)&ffb1iP, g_ffb1i);

    __nv_bfloat16 *posetB, *ctxpermB, *ctxB, *WkT, *WvT, *WaT, *WqT, *WoT, *fw1T, *fw2T,
                  *kPB, *vTB, *atokB, *scoresB, *akvTB, *qB, *aqB, *xB, *nhB, *ggB;
    cudaGetSymbolAddress((void**)&posetB, b_poset);
    cudaGetSymbolAddress((void**)&ctxpermB, b_ctxperm);
    cudaGetSymbolAddress((void**)&ctxB, b_ctx);
    cudaGetSymbolAddress((void**)&WkT, b_WkT);
    cudaGetSymbolAddress((void**)&WvT, b_WvT);
    cudaGetSymbolAddress((void**)&WaT, b_WaT);
    cudaGetSymbolAddress((void**)&WqT, b_WqT);
    cudaGetSymbolAddress((void**)&WoT, b_WoT);
    cudaGetSymbolAddress((void**)&fw1T, b_ffw1T);
    cudaGetSymbolAddress((void**)&fw2T, b_ffw2T);
    cudaGetSymbolAddress((void**)&kPB, b_kP);
    cudaGetSymbolAddress((void**)&vTB, b_vT);
    cudaGetSymbolAddress((void**)&atokB, b_atok);
    cudaGetSymbolAddress((void**)&scoresB, b_scores);
    cudaGetSymbolAddress((void**)&akvTB, b_akvT);
    cudaGetSymbolAddress((void**)&qB, b_q);
    cudaGetSymbolAddress((void**)&aqB, b_aq);
    cudaGetSymbolAddress((void**)&xB, b_x);
    cudaGetSymbolAddress((void**)&nhB, b_nh);
    cudaGetSymbolAddress((void**)&ggB, b_gg);

    const float SCALE = 0.125f;
    auto cdiv = [](long a, long b) { return (int)((a + b - 1) / b); };

    cudaMemcpyAsync(hs, hidden, sizeof(float) * kHS, cudaMemcpyDeviceToDevice, 0);
    poset_k<<<cdiv(kHS, 256), 256>>>(pose, posetB);
    ctxperm_k<<<cdiv((long)kB * 512 * kCD, 256), 256>>>(context, ctxpermB);
    conv_k<<<cdiv((long)kB * kC * kCtok * kCD, 256), 256>>>(context, ctxB, (long)kB * kC * kCtok * kCD);
    tconv_k<<<cdiv((long)2 * kCD * kI, 256), 256>>>(Wk, WkT, kCD, kI, 2);
    tconv_k<<<cdiv((long)2 * kCD * kI, 256), 256>>>(Wv, WvT, kCD, kI, 2);
    tconv_k<<<cdiv((long)2 * kQ * kI, 256), 256>>>(Wa, WaT, kQ, kI, 2);
    tconv_k<<<cdiv((long)2 * kQ * kI, 256), 256>>>(Wq, WqT, kQ, kI, 2);
    tconv_k<<<cdiv((long)2 * kI * kQ, 256), 256>>>(Wo, WoT, kI, kQ, 2);
    w1i_k<<<cdiv((long)2 * kFF * kQ, 256), 256>>>(ff_w1, fw1T);
    b1i_k<<<cdiv(2 * kFF, 256), 256>>>(ff_b1, ffb1iP);
    tconv_k<<<cdiv((long)kFF * kQ, 256), 256>>>(ff_w2, fw2T, kFF, kQ, 1);

    for (int blk = 0; blk < 2; blk++) {
        const __nv_bfloat16* WkT_b = WkT + (size_t)blk * kI * kCD;
        const __nv_bfloat16* WvT_b = WvT + (size_t)blk * kI * kCD;
        const __nv_bfloat16* WaT_b = WaT + (size_t)blk * kI * kQ;
        const __nv_bfloat16* WqT_b = WqT + (size_t)blk * kI * kQ;
        const __nv_bfloat16* WoT_b = WoT + (size_t)blk * kQ * kI;
        const float* ab_b = agent_bias + (size_t)blk * kN * kCtok;
        const float* qb_b = query_bias + (size_t)blk * kN * kN;
        const float* dw_b = dwc_w + (size_t)blk * kI * 9;
        const float* db_b = dwc_b + (size_t)blk * kI;

        // kP (bf16 natural only): [b] 512x512, K=1024
        gemm(ctxpermB, WkT_b, nullptr, nullptr, kPB,
             512, kI, kCD, kCD, kCD, 0, kI,
             512L * kCD, 0, 0, 512L * kI, 1, kB, 1.f, 8 | 32);
        // v proj: fp32 natural + bf16 transposed; [b,c] 256x512, K=1024
        gemm(ctxB, WvT_b, nullptr, vP, vTB,
             kCtok, kI, kCD, kCD, kCD, kI, kCtok,
             (long)kCtok * kCD, 0, (long)kCtok * kI, (long)kI * kCtok, 1, kB * kC, 1.f, 16);
        // a_tok (bf16 natural only): 32768x512, K=320
        gemm(posetB, WaT_b, nullptr, nullptr, atokB,
             (int)kTOK, kI, kQ, kQ, kQ, 0, kI,
             0, 0, 0, 0, 1, 1, 1.f, 8 | 32);
        // scores = SCALE * atok @ kP^T : per (b,t) 1024x512, K=512
        gemm(atokB, kPB, nullptr, scoresP, nullptr,
             kN, 512, kI, kI, kI, 512, 0,
             (long)kN * kI, 512L * kI, (long)kN * 512, 0, kT, kB * kT, SCALE, 0);
        softmax_kv_k<<<dim3(kB * kT * kN, 2), 256>>>(scoresP, ab_b, scoresB);
        // agent_kv = max_c2(probs_c2 @ v_c2): per (b,t) 1024x512, K=256
        gemm(scoresB, vTB, nullptr, akvP, nullptr,
             kN, kI, kCtok, 512, kCtok, kI, 0,
             (long)kN * 512, (long)kC * kI * kCtok, (long)kN * kI, 0, kT, kB * kT, 1.f, 0);
        gemm(scoresB + 256, vTB + (size_t)kI * kCtok, nullptr, akvP, akvTB,
             kN, kI, kCtok, 512, kCtok, kI, kN,
             (long)kN * 512, (long)kC * kI * kCtok, (long)kN * kI, (long)kI * kN, kT, kB * kT, 1.f, 2 | 16);
        // dwconv + upsample
        dwconv_k<<<kB * kCtok, kI>>>(vP, dw_b, db_b, vdP);
        upsample_k<<<kB * kN, kI>>>(vdP, vtokP);
        // LN + q proj (bf16 only)
        ln_k<<<(int)kTOK, 256>>>(hs, norm_w, norm_b, nhB, kQ);
        gemm(nhB, WqT_b, nullptr, nullptr, qB,
             (int)kTOK, kI, kQ, kQ, kQ, 0, kI,
             0, 0, 0, 0, 1, 1, 1.f, 8 | 32);
        // aq = SCALE * q @ atok^T : per (b,t) 1024x1024, K=512
        gemm(qB, atokB, nullptr, aqP, nullptr,
             kN, kN, kI, kI, kI, kN, 0,
             (long)kN * kI, (long)kN * kI, (long)kN * kN, 0, 1, kB * kT, SCALE, 0);
        softmax_aq_k<<<(int)kTOK, 256>>>(aqP, qb_b, aqB);
        // x = aq @ akv : per (b,t) 1024x512, K=1024
        gemm(aqB, akvTB, nullptr, xP, nullptr,
             kN, kI, kN, kN, kN, kI, 0,
             (long)kN * kN, (long)kI * kN, (long)kN * kI, 0, 1, kB * kT, 1.f, 0);
        addvtok_k<<<cdiv(kTOK * kI, 256), 256>>>(xP, vtokP, xB);
        // hs += x @ Wo : 32768x320, K=512
        gemm(xB, WoT_b, nullptr, hs, nullptr,
             (int)kTOK, kQ, kI, kI, kI, kQ, 0,
             0, 0, 0, 0, 1, 1, 1.f, 1);
    }

    // ---- FF: LN -> fused FF1+GEGLU -> FF2, residual ----
    ln_k<<<(int)kTOK, 256>>>(hs, ffln_w, ffln_b, nhB, kQ);
    gemm(nhB, fw1T, ffb1iP, nullptr, ggB,
         (int)kTOK, 2 * kFF, kQ, kQ, kQ, 0, kFF,
         0, 0, 0, 0, 1, 1, 1.f, 4 | 32 | 512);
    gemm(ggB, fw2T, ff_b2, hs, nullptr,
         (int)kTOK, kQ, kFF, kFF, kFF, kQ, 0,
         0, 0, 0, 0, 1, 1, 1.f, 1 | 4);

    cudaMemcpyAsync(d_out, hs, sizeof(float) * kHS, cudaMemcpyDeviceToDevice, 0);
}

// round 9
// speedup vs baseline: 1.2621x; 1.0464x over previous
#include <cuda_runtime.h>
#include <cuda_bf16.h>
#include <math.h>
#include <stdint.h>

// ---------------- problem constants ----------------
constexpr int kB = 2;
constexpr int kT = 16;
constexpr int kN = 1024;
constexpr int kC = 2;
constexpr int kCtok = 256;
constexpr int kQ = 320;
constexpr int kI = 512;
constexpr int kCD = 1024;
constexpr int kFF = 1280;
constexpr long kHS = (long)kB * kT * kN * kQ;
constexpr long kTOK = (long)kB * kT * kN;        // 32768

// ---------------- fp32 scratch ----------------
static __device__ float g_hs[kHS];
static __device__ float g_v[(long)kB * kC * kCtok * kI];
static __device__ float g_scores[kTOK * kI];
static __device__ float g_akv[kTOK * kI];
static __device__ float g_vdmax[(long)kB * kCtok * kI];
static __device__ float g_vtokWo[(long)kB * kN * kQ];
static __device__ float g_aq[kTOK * kN];
static __device__ float g_ffb1i[2 * kFF];

// ---------------- bf16 scratch ----------------
static __device__ __nv_bfloat16 b_poset[kHS];
static __device__ __nv_bfloat16 b_ctxperm[(long)kB * 512 * kCD];
static __device__ __nv_bfloat16 b_ctx[(long)kB * kC * kCtok * kCD];
static __device__ __nv_bfloat16 b_WkT[(long)2 * kI * kCD];
static __device__ __nv_bfloat16 b_WvT[(long)2 * kI * kCD];
static __device__ __nv_bfloat16 b_WaT[(long)2 * kI * kQ];
static __device__ __nv_bfloat16 b_WqT[(long)2 * kI * kQ];
static __device__ __nv_bfloat16 b_WoT[(long)2 * kQ * kI];
static __device__ __nv_bfloat16 b_ffw1T[(long)2 * kFF * kQ];   // interleaved a/g pairs
static __device__ __nv_bfloat16 b_ffw2T[(long)kQ * kFF];
static __device__ __nv_bfloat16 b_kP[(long)kB * 512 * kI];
static __device__ __nv_bfloat16 b_vT[(long)kB * kC * kI * kCtok];
static __device__ __nv_bfloat16 b_atok[kTOK * kI];
static __device__ __nv_bfloat16 b_scores[kTOK * kI];
static __device__ __nv_bfloat16 b_akv[kTOK * kI];              // natural [m][e] per (b,t)
static __device__ __nv_bfloat16 b_akvWoT[(long)kB * kT * kQ * kN]; // transposed [d][m] per (b,t)
static __device__ __nv_bfloat16 b_q[kTOK * kI];
static __device__ __nv_bfloat16 b_aq[kTOK * kN];
static __device__ __nv_bfloat16 b_vtok[(long)kB * kN * kI];
static __device__ __nv_bfloat16 b_nh[kHS];
static __device__ __nv_bfloat16 b_gg[kTOK * kFF];

// ---------------- PTX helpers ----------------
__device__ __forceinline__ uint32_t smem_u32(const void* p) {
    return (uint32_t)__cvta_generic_to_shared(p);
}
__device__ __forceinline__ void cp16(uint32_t dst, const void* src, int src_bytes) {
    asm volatile("cp.async.cg.shared.global [%0], [%1], 16, %2;\n"
                 :: "r"(dst), "l"(src), "r"(src_bytes));
}
__device__ __forceinline__ void cp_commit() { asm volatile("cp.async.commit_group;\n"); }
template<int W> __device__ __forceinline__ void cp_wait() {
    asm volatile("cp.async.wait_group %0;\n" :: "n"(W));
}
__device__ __forceinline__ void mma16(float* d, const uint32_t* a, const uint32_t* b) {
    asm volatile(
        "mma.sync.aligned.m16n8k16.row.col.f32.bf16.bf16.f32 "
        "{%0,%1,%2,%3},{%4,%5,%6,%7},{%8,%9},{%0,%1,%2,%3};"
        : "+f"(d[0]), "+f"(d[1]), "+f"(d[2]), "+f"(d[3])
        : "r"(a[0]), "r"(a[1]), "r"(a[2]), "r"(a[3]), "r"(b[0]), "r"(b[1]));
}

// ---------------- bf16 NT tensor-core GEMM ----------------
// C(MxN) = alpha * A(MxK,bf16,row) * B(NxK,bf16,row)^T + epilogues.
// flags: 1 += C ; 2 max C ; 4 += bias[col] ; 8 write bf16 natural Cb ;
//        16 write bf16 transposed Cb ; 32 suppress fp32 write ;
//        256 += aux[((z>>4)*1024 + row)*ldaux + col]   (t-broadcast aux)
//        512 GEGLU pair epilogue: cols interleaved (even=a, odd=g),
//            writes bf16 a*gelu(g) to Cb at column col/2 (ldcb = N/2).
// Requires M%128==0, K%32==0, lda/ldb %8==0. N guarded (except flag 512: N%128==0).
constexpr int SSTR = 40;   // bf16 smem row stride (80B, conflict-free)

__global__ __launch_bounds__(256, 2)
void bgemm_k(const __nv_bfloat16* __restrict__ A, const __nv_bfloat16* __restrict__ Bm,
             const float* __restrict__ bias, const float* __restrict__ aux,
             float* __restrict__ C, __nv_bfloat16* __restrict__ Cb,
             int M, int N, int K, int lda, int ldb, int ldc, int ldcb, int ldaux,
             long strA, long strB, long strC, long strCb,
             int bDiv, float alpha, int flags)
{
    __shared__ __align__(16) __nv_bfloat16 sA[2][128 * SSTR];
    __shared__ __align__(16) __nv_bfloat16 sB[2][128 * SSTR];

    const int z = blockIdx.z;
    const __nv_bfloat16* Ap = A + (size_t)z * strA;
    const __nv_bfloat16* Bp = Bm + (size_t)(z / bDiv) * strB;
    float* Cp = C + (size_t)z * strC;
    __nv_bfloat16* Cbp = Cb + (size_t)z * strCb;
    const int m0 = blockIdx.y * 128, n0 = blockIdx.x * 128;
    const int tid = threadIdx.x;
    const int lane = tid & 31, warp = tid >> 5;
    const int wm = warp & 1, wn = warp >> 1;      // 2x4 warps; warp tile 64x32
    const int gid = lane >> 2, tig = lane & 3;

    float acc[4][4][4];
    #pragma unroll
    for (int i = 0; i < 4; i++)
        #pragma unroll
        for (int j = 0; j < 4; j++)
            #pragma unroll
            for (int r = 0; r < 4; r++) acc[i][j][r] = 0.f;

    const int kTiles = K >> 5;

    auto load_tile = [&](int buf, int kt) {
        const int k0 = kt << 5;
        #pragma unroll
        for (int j = 0; j < 2; j++) {
            int i = tid + 256 * j;
            int r = i >> 2, c = i & 3;
            cp16(smem_u32(&sA[buf][r * SSTR + c * 8]),
                 Ap + (size_t)(m0 + r) * lda + k0 + c * 8, 16);
        }
        #pragma unroll
        for (int j = 0; j < 2; j++) {
            int i = tid + 256 * j;
            int r = i >> 2, c = i & 3;
            int gn = n0 + r;
            cp16(smem_u32(&sB[buf][r * SSTR + c * 8]),
                 Bp + (size_t)gn * ldb + k0 + c * 8, gn < N ? 16 : 0);
        }
        cp_commit();
    };

    auto compute_tile = [&](int buf) {
        #pragma unroll
        for (int s = 0; s < 2; s++) {
            const int kk = s * 16;
            uint32_t af[4][4], bf[4][2];
            #pragma unroll
            for (int mt = 0; mt < 4; mt++) {
                int rm = wm * 64 + mt * 16;
                const __nv_bfloat16* base = &sA[buf][(rm + gid) * SSTR + kk + 2 * tig];
                af[mt][0] = *(const uint32_t*)(base);
                af[mt][1] = *(const uint32_t*)(base + 8 * SSTR);
                af[mt][2] = *(const uint32_t*)(base + 8);
                af[mt][3] = *(const uint32_t*)(base + 8 * SSTR + 8);
            }
            #pragma unroll
            for (int nt = 0; nt < 4; nt++) {
                int cb = wn * 32 + nt * 8 + gid;
                const __nv_bfloat16* base = &sB[buf][cb * SSTR + kk + 2 * tig];
                bf[nt][0] = *(const uint32_t*)(base);
                bf[nt][1] = *(const uint32_t*)(base + 8);
            }
            #pragma unroll
            for (int mt = 0; mt < 4; mt++)
                #pragma unroll
                for (int nt = 0; nt < 4; nt++)
                    mma16(acc[mt][nt], af[mt], bf[nt]);
        }
    };

    load_tile(0, 0);
    for (int kt = 0; kt < kTiles; kt++) {
        if (kt + 1 < kTiles) {
            load_tile((kt + 1) & 1, kt + 1);
            cp_wait<1>();
        } else {
            cp_wait<0>();
        }
        __syncthreads();
        compute_tile(kt & 1);
        __syncthreads();
    }

    // epilogue
    #pragma unroll
    for (int mt = 0; mt < 4; mt++) {
        #pragma unroll
        for (int nt = 0; nt < 4; nt++) {
            int row0 = m0 + wm * 64 + mt * 16 + gid;
            int col0 = n0 + wn * 32 + nt * 8 + tig * 2;
            if (flags & 512) {
                float ba = bias[col0], bg = bias[col0 + 1];
                #pragma unroll
                for (int h = 0; h < 2; h++) {
                    int rr = row0 + h * 8;
                    float a = alpha * acc[mt][nt][2 * h] + ba;
                    float g = alpha * acc[mt][nt][2 * h + 1] + bg;
                    float gg = a * 0.5f * g * (1.f + erff(g * 0.70710678118654752f));
                    Cbp[(size_t)rr * ldcb + (col0 >> 1)] = __float2bfloat16(gg);
                }
                continue;
            }
            #pragma unroll
            for (int r = 0; r < 4; r++) {
                int rr = row0 + (r >> 1) * 8;
                int cc = col0 + (r & 1);
                if (cc >= N) continue;
                float vv = alpha * acc[mt][nt][r];
                size_t off = (size_t)rr * ldc + cc;
                if (flags & 4)   vv += bias[cc];
                if (flags & 256) vv += aux[(((size_t)(z >> 4)) * 1024 + rr) * ldaux + cc];
                if (flags & 1) vv += Cp[off];
                if (flags & 2) vv = fmaxf(vv, Cp[off]);
                if (!(flags & 32)) Cp[off] = vv;
                if (flags & 8)  Cbp[(size_t)rr * ldcb + cc] = __float2bfloat16(vv);
                if (flags & 16) Cbp[(size_t)cc * ldcb + rr] = __float2bfloat16(vv);
            }
        }
    }
}

static void gemm(const __nv_bfloat16* A, const __nv_bfloat16* B, const float* bias,
                 const float* aux, float* C, __nv_bfloat16* Cb,
                 int M, int N, int K, int lda, int ldb, int ldc, int ldcb, int ldaux,
                 long sA, long sB, long sC, long sCb, int bDiv, int batch,
                 float alpha, int flags)
{
    dim3 gr((N + 127) / 128, M / 128, batch);
    bgemm_k<<<gr, 256>>>(A, B, bias, aux, C, Cb, M, N, K,
                         lda, ldb, ldc, ldcb, ldaux,
                         sA, sB, sC, sCb, bDiv, alpha, flags);
}

// ---------------- LayerNorm (bf16 out) ----------------
__global__ void ln_k(const float* __restrict__ x, const float* __restrict__ w,
                     const float* __restrict__ b, __nv_bfloat16* __restrict__ y, int cols)
{
    int row = blockIdx.x;
    const float* xp = x + (size_t)row * cols;
    float s1 = 0.f, s2 = 0.f;
    for (int i = threadIdx.x; i < cols; i += blockDim.x) {
        float v = xp[i]; s1 += v; s2 += v * v;
    }
    __shared__ float r1[256], r2[256];
    r1[threadIdx.x] = s1; r2[threadIdx.x] = s2;
    __syncthreads();
    for (int s = 128; s > 0; s >>= 1) {
        if (threadIdx.x < s) { r1[threadIdx.x] += r1[threadIdx.x + s]; r2[threadIdx.x] += r2[threadIdx.x + s]; }
        __syncthreads();
    }
    float mean = r1[0] / cols;
    float var = r2[0] / cols - mean * mean;
    float rstd = rsqrtf(var + 1e-5f);
    __nv_bfloat16* yp = y + (size_t)row * cols;
    for (int i = threadIdx.x; i < cols; i += blockDim.x)
        yp[i] = __float2bfloat16((xp[i] - mean) * rstd * w[i] + b[i]);
}

// ---------------- softmax kv groups (256 cols, + agent_bias[m,nc2]) -> bf16 ----------------
__global__ void softmax_kv_k(const float* __restrict__ s, const float* __restrict__ abias,
                             __nv_bfloat16* __restrict__ ob)
{
    int gr = blockIdx.x;
    int c2 = blockIdx.y;
    int m = gr & 1023;
    const float* p = s + (size_t)gr * 512 + c2 * 256;
    __nv_bfloat16* po = ob + (size_t)gr * 512 + c2 * 256;
    int tid = threadIdx.x;
    float v = p[tid] + abias[(size_t)m * 256 + tid];
    __shared__ float red[256];
    red[tid] = v; __syncthreads();
    for (int st = 128; st; st >>= 1) { if (tid < st) red[tid] = fmaxf(red[tid], red[tid + st]); __syncthreads(); }
    float mx = red[0]; __syncthreads();
    float e = __expf(v - mx);
    red[tid] = e; __syncthreads();
    for (int st = 128; st; st >>= 1) { if (tid < st) red[tid] += red[tid + st]; __syncthreads(); }
    po[tid] = __float2bfloat16(e / red[0]);
}

// ---------------- softmax query rows (1024 cols, + query_bias[n,m]) -> bf16 ----------------
__global__ void softmax_aq_k(const float* __restrict__ s, const float* __restrict__ qbias,
                             __nv_bfloat16* __restrict__ ob)
{
    int gr = blockIdx.x;
    int n = gr & 1023;
    const float* p = s + (size_t)gr * 1024;
    __nv_bfloat16* po = ob + (size_t)gr * 1024;
    const float* bp = qbias + (size_t)n * 1024;
    int tid = threadIdx.x;
    float v[4];
    float mx = -1e30f;
    #pragma unroll
    for (int k = 0; k < 4; k++) { v[k] = p[tid + k * 256] + bp[tid + k * 256]; mx = fmaxf(mx, v[k]); }
    __shared__ float red[256];
    red[tid] = mx; __syncthreads();
    for (int st = 128; st; st >>= 1) { if (tid < st) red[tid] = fmaxf(red[tid], red[tid + st]); __syncthreads(); }
    mx = red[0]; __syncthreads();
    float sum = 0.f;
    #pragma unroll
    for (int k = 0; k < 4; k++) { v[k] = __expf(v[k] - mx); sum += v[k]; }
    red[tid] = sum; __syncthreads();
    for (int st = 128; st; st >>= 1) { if (tid < st) red[tid] += red[tid + st]; __syncthreads(); }
    float inv = 1.f / red[0];
    #pragma unroll
    for (int k = 0; k < 4; k++) po[tid + k * 256] = __float2bfloat16(v[k] * inv);
}

// ---------------- pose transpose -> bf16 ----------------
__global__ void poset_k(const float* __restrict__ pose, __nv_bfloat16* __restrict__ out)
{
    long idx = (long)blockIdx.x * blockDim.x + threadIdx.x;
    if (idx >= kHS) return;
    int d = (int)(idx % kQ);
    long r = idx / kQ;
    int n = (int)(r % kN); r /= kN;
    int t = (int)(r % kT); int b = (int)(r / kT);
    int h = n >> 5, w = n & 31;
    out[idx] = __float2bfloat16(pose[(((((size_t)b * kQ + d) * kT + t) * 32 + h) * 32) + w]);
}

// ---------------- context permuted rows -> bf16 ----------------
__global__ void ctxperm_k(const float* __restrict__ ctx, __nv_bfloat16* __restrict__ out)
{
    long idx = (long)blockIdx.x * blockDim.x + threadIdx.x;
    if (idx >= (long)kB * 512 * kCD) return;
    int k = (int)(idx % kCD);
    long r0 = idx / kCD;
    int r = (int)(r0 % 512); int b = (int)(r0 / 512);
    int n = ((r & 255) << 1) | (r >> 8);
    out[idx] = __float2bfloat16(ctx[(((size_t)b * kC + (n >> 8)) * kCtok + (n & 255)) * kCD + k]);
}

// ---------------- plain fp32->bf16 convert ----------------
__global__ void conv_k(const float* __restrict__ s, __nv_bfloat16* __restrict__ d, long n)
{
    long idx = (long)blockIdx.x * blockDim.x + threadIdx.x;
    if (idx < n) d[idx] = __float2bfloat16(s[idx]);
}

// ---------------- transpose convert: dst[b][c][r] = src[b][r][c] ----------------
__global__ void tconv_k(const float* __restrict__ s, __nv_bfloat16* __restrict__ d,
                        int R, int Cc, int batch)
{
    long n = (long)R * Cc * batch;
    long idx = (long)blockIdx.x * blockDim.x + threadIdx.x;
    if (idx >= n) return;
    int r = (int)(idx % R);
    long q = idx / R;
    int c = (int)(q % Cc);
    int b = (int)(q / Cc);
    d[idx] = __float2bfloat16(s[((size_t)b * R + r) * Cc + c]);
}

// ---------------- FF1 weight transpose with a/g column interleave ----------------
__global__ void w1i_k(const float* __restrict__ s, __nv_bfloat16* __restrict__ d)
{
    long n = (long)2 * kFF * kQ;
    long idx = (long)blockIdx.x * blockDim.x + threadIdx.x;
    if (idx >= n) return;
    int k = (int)(idx % kQ);
    int e = (int)(idx / kQ);
    int oc = (e & 1) ? (kFF + (e >> 1)) : (e >> 1);
    d[idx] = __float2bfloat16(s[(size_t)k * (2 * kFF) + oc]);
}
__global__ void b1i_k(const float* __restrict__ s, float* __restrict__ d)
{
    int e = blockIdx.x * blockDim.x + threadIdx.x;
    if (e >= 2 * kFF) return;
    int oc = (e & 1) ? (kFF + (e >> 1)) : (e >> 1);
    d[e] = s[oc];
}

// ---------------- depthwise 3x3 conv + frame max + bias ----------------
__global__ void dwconv_k(const float* __restrict__ v, const float* __restrict__ wgt,
                         const float* __restrict__ bias, float* __restrict__ out)
{
    int pix = blockIdx.x & 255;
    int b = blockIdx.x >> 8;
    int e = threadIdx.x;
    int h = pix >> 4, w = pix & 15;
    float wv[9];
    #pragma unroll
    for (int t9 = 0; t9 < 9; t9++) wv[t9] = wgt[e * 9 + t9];
    float best = -1e30f;
    #pragma unroll
    for (int c = 0; c < 2; c++) {
        float s = 0.f;
        #pragma unroll
        for (int dh = -1; dh <= 1; dh++)
            #pragma unroll
            for (int dw = -1; dw <= 1; dw++) {
                int hh = h + dh, ww = w + dw;
                if (hh < 0 || hh > 15 || ww < 0 || ww > 15) continue;
                s += v[((size_t)(b * kC + c) * kCtok + hh * 16 + ww) * kI + e] * wv[(dh + 1) * 3 + (dw + 1)];
            }
        best = fmaxf(best, s);
    }
    out[((size_t)b * kCtok + pix) * kI + e] = best + bias[e];
}

// ---------------- bilinear x2 upsample -> bf16 ----------------
__global__ void upsample_k(const float* __restrict__ vd, __nv_bfloat16* __restrict__ vtok)
{
    int opix = blockIdx.x & 1023;
    int b = blockIdx.x >> 10;
    int e = threadIdx.x;
    int y = opix >> 5, x = opix & 31;
    int py = y >> 1, px = x >> 1;
    int y0, y1, x0, x1; float wy0, wy1, wx0, wx1;
    if (y & 1) { y0 = py; y1 = min(py + 1, 15); wy0 = 0.75f; wy1 = 0.25f; }
    else       { y0 = max(py - 1, 0); y1 = py;  wy0 = 0.25f; wy1 = 0.75f; }
    if (x & 1) { x0 = px; x1 = min(px + 1, 15); wx0 = 0.75f; wx1 = 0.25f; }
    else       { x0 = max(px - 1, 0); x1 = px;  wx0 = 0.25f; wx1 = 0.75f; }
    const float* base = vd + (size_t)b * kCtok * kI;
    float r = wy0 * wx0 * base[(size_t)(y0 * 16 + x0) * kI + e]
            + wy0 * wx1 * base[(size_t)(y0 * 16 + x1) * kI + e]
            + wy1 * wx0 * base[(size_t)(y1 * 16 + x0) * kI + e]
            + wy1 * wx1 * base[(size_t)(y1 * 16 + x1) * kI + e];
    vtok[((size_t)b * kN + opix) * kI + e] = __float2bfloat16(r);
}

// ---------------- launch ----------------
extern "C" void kernel_launch(void* const* d_in, const int* in_sizes, int n_in,
                              void* d_out, int out_size)
{
    const float* hidden     = (const float*)d_in[0];
    const float* context    = (const float*)d_in[1];
    const float* pose       = (const float*)d_in[2];
    const float* Wq         = (const float*)d_in[3];
    const float* Wk         = (const float*)d_in[4];
    const float* Wv         = (const float*)d_in[5];
    const float* Wa         = (const float*)d_in[6];
    const float* agent_bias = (const float*)d_in[7];
    const float* query_bias = (const float*)d_in[8];
    const float* dwc_w      = (const float*)d_in[9];
    const float* dwc_b      = (const float*)d_in[10];
    const float* Wo         = (const float*)d_in[11];
    const float* norm_w     = (const float*)d_in[12];
    const float* norm_b     = (const float*)d_in[13];
    const float* ffln_w     = (const float*)d_in[14];
    const float* ffln_b     = (const float*)d_in[15];
    const float* ff_w1      = (const float*)d_in[16];
    const float* ff_b1      = (const float*)d_in[17];
    const float* ff_w2      = (const float*)d_in[18];
    const float* ff_b2      = (const float*)d_in[19];

    float *hs, *vP, *scoresP, *akvP, *vdP, *vtokWoP, *aqP, *ffb1iP;
    cudaGetSymbolAddress((void**)&hs, g_hs);
    cudaGetSymbolAddress((void**)&vP, g_v);
    cudaGetSymbolAddress((void**)&scoresP, g_scores);
    cudaGetSymbolAddress((void**)&akvP, g_akv);
    cudaGetSymbolAddress((void**)&vdP, g_vdmax);
    cudaGetSymbolAddress((void**)&vtokWoP, g_vtokWo);
    cudaGetSymbolAddress((void**)&aqP, g_aq);
    cudaGetSymbolAddress((void**)&ffb1iP, g_ffb1i);

    __nv_bfloat16 *posetB, *ctxpermB, *ctxB, *WkT, *WvT, *WaT, *WqT, *WoT, *fw1T, *fw2T,
                  *kPB, *vTB, *atokB, *scoresB, *akvB, *akvWoT, *qB, *aqB, *vtokB, *nhB, *ggB;
    cudaGetSymbolAddress((void**)&posetB, b_poset);
    cudaGetSymbolAddress((void**)&ctxpermB, b_ctxperm);
    cudaGetSymbolAddress((void**)&ctxB, b_ctx);
    cudaGetSymbolAddress((void**)&WkT, b_WkT);
    cudaGetSymbolAddress((void**)&WvT, b_WvT);
    cudaGetSymbolAddress((void**)&WaT, b_WaT);
    cudaGetSymbolAddress((void**)&WqT, b_WqT);
    cudaGetSymbolAddress((void**)&WoT, b_WoT);
    cudaGetSymbolAddress((void**)&fw1T, b_ffw1T);
    cudaGetSymbolAddress((void**)&fw2T, b_ffw2T);
    cudaGetSymbolAddress((void**)&kPB, b_kP);
    cudaGetSymbolAddress((void**)&vTB, b_vT);
    cudaGetSymbolAddress((void**)&atokB, b_atok);
    cudaGetSymbolAddress((void**)&scoresB, b_scores);
    cudaGetSymbolAddress((void**)&akvB, b_akv);
    cudaGetSymbolAddress((void**)&akvWoT, b_akvWoT);
    cudaGetSymbolAddress((void**)&qB, b_q);
    cudaGetSymbolAddress((void**)&aqB, b_aq);
    cudaGetSymbolAddress((void**)&vtokB, b_vtok);
    cudaGetSymbolAddress((void**)&nhB, b_nh);
    cudaGetSymbolAddress((void**)&ggB, b_gg);

    const float SCALE = 0.125f;
    auto cdiv = [](long a, long b) { return (int)((a + b - 1) / b); };

    cudaMemcpyAsync(hs, hidden, sizeof(float) * kHS, cudaMemcpyDeviceToDevice, 0);
    poset_k<<<cdiv(kHS, 256), 256>>>(pose, posetB);
    ctxperm_k<<<cdiv((long)kB * 512 * kCD, 256), 256>>>(context, ctxpermB);
    conv_k<<<cdiv((long)kB * kC * kCtok * kCD, 256), 256>>>(context, ctxB, (long)kB * kC * kCtok * kCD);
    tconv_k<<<cdiv((long)2 * kCD * kI, 256), 256>>>(Wk, WkT, kCD, kI, 2);
    tconv_k<<<cdiv((long)2 * kCD * kI, 256), 256>>>(Wv, WvT, kCD, kI, 2);
    tconv_k<<<cdiv((long)2 * kQ * kI, 256), 256>>>(Wa, WaT, kQ, kI, 2);
    tconv_k<<<cdiv((long)2 * kQ * kI, 256), 256>>>(Wq, WqT, kQ, kI, 2);
    tconv_k<<<cdiv((long)2 * kI * kQ, 256), 256>>>(Wo, WoT, kI, kQ, 2);
    w1i_k<<<cdiv((long)2 * kFF * kQ, 256), 256>>>(ff_w1, fw1T);
    b1i_k<<<cdiv(2 * kFF, 256), 256>>>(ff_b1, ffb1iP);
    tconv_k<<<cdiv((long)kFF * kQ, 256), 256>>>(ff_w2, fw2T, kFF, kQ, 1);

    for (int blk = 0; blk < 2; blk++) {
        const __nv_bfloat16* WkT_b = WkT + (size_t)blk * kI * kCD;
        const __nv_bfloat16* WvT_b = WvT + (size_t)blk * kI * kCD;
        const __nv_bfloat16* WaT_b = WaT + (size_t)blk * kI * kQ;
        const __nv_bfloat16* WqT_b = WqT + (size_t)blk * kI * kQ;
        const __nv_bfloat16* WoT_b = WoT + (size_t)blk * kQ * kI;
        const float* ab_b = agent_bias + (size_t)blk * kN * kCtok;
        const float* qb_b = query_bias + (size_t)blk * kN * kN;
        const float* dw_b = dwc_w + (size_t)blk * kI * 9;
        const float* db_b = dwc_b + (size_t)blk * kI;

        // kP (bf16 natural only): [b] 512x512, K=1024
        gemm(ctxpermB, WkT_b, nullptr, nullptr, nullptr, kPB,
             512, kI, kCD, kCD, kCD, 0, kI, 0,
             512L * kCD, 0, 0, 512L * kI, 1, kB, 1.f, 8 | 32);
        // v proj: fp32 natural + bf16 transposed; [b,c] 256x512, K=1024
        gemm(ctxB, WvT_b, nullptr, nullptr, vP, vTB,
             kCtok, kI, kCD, kCD, kCD, kI, kCtok, 0,
             (long)kCtok * kCD, 0, (long)kCtok * kI, (long)kI * kCtok, 1, kB * kC, 1.f, 16);
        // a_tok (bf16 natural only): 32768x512, K=320
        gemm(posetB, WaT_b, nullptr, nullptr, nullptr, atokB,
             (int)kTOK, kI, kQ, kQ, kQ, 0, kI, 0,
             0, 0, 0, 0, 1, 1, 1.f, 8 | 32);
        // scores = SCALE * atok @ kP^T : per (b,t) 1024x512, K=512
        gemm(atokB, kPB, nullptr, nullptr, scoresP, nullptr,
             kN, 512, kI, kI, kI, 512, 0, 0,
             (long)kN * kI, 512L * kI, (long)kN * 512, 0, kT, kB * kT, SCALE, 0);
        softmax_kv_k<<<dim3(kB * kT * kN, 2), 256>>>(scoresP, ab_b, scoresB);
        // agent_kv = max_c2(probs_c2 @ v_c2): per (b,t) 1024x512, K=256
        gemm(scoresB, vTB, nullptr, nullptr, akvP, nullptr,
             kN, kI, kCtok, 512, kCtok, kI, 0, 0,
             (long)kN * 512, (long)kC * kI * kCtok, (long)kN * kI, 0, kT, kB * kT, 1.f, 0);
        gemm(scoresB + 256, vTB + (size_t)kI * kCtok, nullptr, nullptr, akvP, akvB,
             kN, kI, kCtok, 512, kCtok, kI, kI, 0,
             (long)kN * 512, (long)kC * kI * kCtok, (long)kN * kI, (long)kN * kI, kT, kB * kT,
             1.f, 2 | 8 | 32);
        // akvWo^T (bf16 transposed): per (b,t) [1024x320] from akv[1024x512] @ Wo
        gemm(akvB, WoT_b, nullptr, nullptr, akvP, akvWoT,
             kN, kQ, kI, kI, kI, kQ, kN, 0,
             (long)kN * kI, 0, 0, (long)kQ * kN, 1, kB * kT, 1.f, 16 | 32);
        // dwconv + upsample (bf16 v_tok)
        dwconv_k<<<kB * kCtok, kI>>>(vP, dw_b, db_b, vdP);
        upsample_k<<<kB * kN, kI>>>(vdP, vtokB);
        // vtokWo = v_tok @ Wo : per b, 1024x320, K=512 (fp32)
        gemm(vtokB, WoT_b, nullptr, nullptr, vtokWoP, nullptr,
             kN, kQ, kI, kI, kI, kQ, 0, 0,
             (long)kN * kI, 0, (long)kN * kQ, 0, 1, kB, 1.f, 0);
        // LN + q proj (bf16 only)
        ln_k<<<(int)kTOK, 256>>>(hs, norm_w, norm_b, nhB, kQ);
        gemm(nhB, WqT_b, nullptr, nullptr, nullptr, qB,
             (int)kTOK, kI, kQ, kQ, kQ, 0, kI, 0,
             0, 0, 0, 0, 1, 1, 1.f, 8 | 32);
        // aq = SCALE * q @ atok^T : per (b,t) 1024x1024, K=512
        gemm(qB, atokB, nullptr, nullptr, aqP, nullptr,
             kN, kN, kI, kI, kI, kN, 0, 0,
             (long)kN * kI, (long)kN * kI, (long)kN * kN, 0, 1, kB * kT, SCALE, 0);
        softmax_aq_k<<<(int)kTOK, 256>>>(aqP, qb_b, aqB);
        // hs += aq @ akvWo + vtokWo : per (b,t) 1024x320, K=1024
        gemm(aqB, akvWoT, nullptr, vtokWoP, hs, nullptr,
             kN, kQ, kN, kN, kN, kQ, 0, kQ,
             (long)kN * kN, (long)kQ * kN, (long)kN * kQ, 0, 1, kB * kT,
             1.f, 1 | 256);
    }

    // ---- FF: LN -> fused FF1+GEGLU -> FF2, residual ----
    ln_k<<<(int)kTOK, 256>>>(hs, ffln_w, ffln_b, nhB, kQ);
    gemm(nhB, fw1T, ffb1iP, nullptr, nullptr, ggB,
         (int)kTOK, 2 * kFF, kQ, kQ, kQ, 0, kFF, 0,
         0, 0, 0, 0, 1, 1, 1.f, 4 | 32 | 512);
    gemm(ggB, fw2T, ff_b2, nullptr, hs, nullptr,
         (int)kTOK, kQ, kFF, kFF, kFF, kQ, 0, 0,
         0, 0, 0, 0, 1, 1, 1.f, 1 | 4);

    cudaMemcpyAsync(d_out, hs, sizeof(float) * kHS, cudaMemcpyDeviceToDevice, 0);
}

// round 10
// speedup vs baseline: 1.3625x; 1.0795x over previous
#include <cuda_runtime.h>
#include <cuda_bf16.h>
#include <math.h>
#include <stdint.h>

// ---------------- problem constants ----------------
constexpr int kB = 2;
constexpr int kT = 16;
constexpr int kN = 1024;
constexpr int kC = 2;
constexpr int kCtok = 256;
constexpr int kQ = 320;
constexpr int kI = 512;
constexpr int kCD = 1024;
constexpr int kFF = 1280;
constexpr long kHS = (long)kB * kT * kN * kQ;
constexpr long kTOK = (long)kB * kT * kN;        // 32768

// ---------------- fp32 scratch ----------------
static __device__ float g_hs[kHS];
static __device__ float g_v[(long)kB * kC * kCtok * kI];
static __device__ float g_scores[kTOK * kI];
static __device__ float g_akv[kTOK * kI];
static __device__ float g_vdmax[(long)kB * kCtok * kI];
static __device__ float g_vtokWo[(long)kB * kN * kQ];
static __device__ float g_aq[kTOK * kN];
static __device__ float g_ffb1i[2 * kFF];

// ---------------- bf16 scratch ----------------
static __device__ __nv_bfloat16 b_poset[kHS];
static __device__ __nv_bfloat16 b_ctxperm[(long)kB * 512 * kCD];
static __device__ __nv_bfloat16 b_ctx[(long)kB * kC * kCtok * kCD];
static __device__ __nv_bfloat16 b_WkT[(long)2 * kI * kCD];
static __device__ __nv_bfloat16 b_WvT[(long)2 * kI * kCD];
static __device__ __nv_bfloat16 b_Wanat[(long)2 * kQ * kI];      // Wa natural (320x512)
static __device__ __nv_bfloat16 b_Wqpad[(long)2 * 384 * kI];     // Wq natural, rows padded to 384
static __device__ __nv_bfloat16 b_WoT[(long)2 * kQ * kI];
static __device__ __nv_bfloat16 b_ffw1T[(long)2 * kFF * kQ];     // interleaved a/g pairs
static __device__ __nv_bfloat16 b_ffw2T[(long)kQ * kFF];
static __device__ __nv_bfloat16 b_kP[(long)kB * 512 * kI];
static __device__ __nv_bfloat16 b_vT[(long)kB * kC * kI * kCtok];
static __device__ __nv_bfloat16 b_S[(long)kB * 512 * kQ];        // kP @ Wa^T  (512x320 per b)
static __device__ __nv_bfloat16 b_GT[(long)2 * kQ * 384];        // (Wq@Wa^T)^T, ld 384
static __device__ __nv_bfloat16 b_U[kTOK * kQ];                  // nh @ G^T
static __device__ __nv_bfloat16 b_scores[kTOK * kI];
static __device__ __nv_bfloat16 b_akv[kTOK * kI];
static __device__ __nv_bfloat16 b_akvWoT[(long)kB * kT * kQ * kN];
static __device__ __nv_bfloat16 b_aq[kTOK * kN];
static __device__ __nv_bfloat16 b_vtok[(long)kB * kN * kI];
static __device__ __nv_bfloat16 b_nh[kHS];
static __device__ __nv_bfloat16 b_gg[kTOK * kFF];

// ---------------- PTX helpers ----------------
__device__ __forceinline__ uint32_t smem_u32(const void* p) {
    return (uint32_t)__cvta_generic_to_shared(p);
}
__device__ __forceinline__ void cp16(uint32_t dst, const void* src, int src_bytes) {
    asm volatile("cp.async.cg.shared.global [%0], [%1], 16, %2;\n"
                 :: "r"(dst), "l"(src), "r"(src_bytes));
}
__device__ __forceinline__ void cp_commit() { asm volatile("cp.async.commit_group;\n"); }
template<int W> __device__ __forceinline__ void cp_wait() {
    asm volatile("cp.async.wait_group %0;\n" :: "n"(W));
}
__device__ __forceinline__ void mma16(float* d, const uint32_t* a, const uint32_t* b) {
    asm volatile(
        "mma.sync.aligned.m16n8k16.row.col.f32.bf16.bf16.f32 "
        "{%0,%1,%2,%3},{%4,%5,%6,%7},{%8,%9},{%0,%1,%2,%3};"
        : "+f"(d[0]), "+f"(d[1]), "+f"(d[2]), "+f"(d[3])
        : "r"(a[0]), "r"(a[1]), "r"(a[2]), "r"(a[3]), "r"(b[0]), "r"(b[1]));
}

// ---------------- bf16 NT tensor-core GEMM ----------------
// C(MxN) = alpha * A(MxK,bf16,row) * B(NxK,bf16,row)^T + epilogues.
// flags: 1 += C ; 2 max C ; 4 += bias[col] ; 8 write bf16 natural Cb ;
//        16 write bf16 transposed Cb ; 32 suppress fp32 write ;
//        256 += aux[((z>>4)*1024 + row)*ldaux + col]   (t-broadcast aux)
//        512 GEGLU pair epilogue: cols interleaved (even=a, odd=g),
//            writes bf16 a*gelu(g) to Cb at column col/2 (ldcb = N/2).
// Requires M%128==0, K%32==0, lda/ldb %8==0. N guarded (except flag 512: N%128==0).
constexpr int SSTR = 40;   // bf16 smem row stride (80B, conflict-free)

__global__ __launch_bounds__(256, 2)
void bgemm_k(const __nv_bfloat16* __restrict__ A, const __nv_bfloat16* __restrict__ Bm,
             const float* __restrict__ bias, const float* __restrict__ aux,
             float* __restrict__ C, __nv_bfloat16* __restrict__ Cb,
             int M, int N, int K, int lda, int ldb, int ldc, int ldcb, int ldaux,
             long strA, long strB, long strC, long strCb,
             int bDiv, float alpha, int flags)
{
    __shared__ __align__(16) __nv_bfloat16 sA[2][128 * SSTR];
    __shared__ __align__(16) __nv_bfloat16 sB[2][128 * SSTR];

    const int z = blockIdx.z;
    const __nv_bfloat16* Ap = A + (size_t)z * strA;
    const __nv_bfloat16* Bp = Bm + (size_t)(z / bDiv) * strB;
    float* Cp = C + (size_t)z * strC;
    __nv_bfloat16* Cbp = Cb + (size_t)z * strCb;
    const int m0 = blockIdx.y * 128, n0 = blockIdx.x * 128;
    const int tid = threadIdx.x;
    const int lane = tid & 31, warp = tid >> 5;
    const int wm = warp & 1, wn = warp >> 1;      // 2x4 warps; warp tile 64x32
    const int gid = lane >> 2, tig = lane & 3;

    float acc[4][4][4];
    #pragma unroll
    for (int i = 0; i < 4; i++)
        #pragma unroll
        for (int j = 0; j < 4; j++)
            #pragma unroll
            for (int r = 0; r < 4; r++) acc[i][j][r] = 0.f;

    const int kTiles = K >> 5;

    auto load_tile = [&](int buf, int kt) {
        const int k0 = kt << 5;
        #pragma unroll
        for (int j = 0; j < 2; j++) {
            int i = tid + 256 * j;
            int r = i >> 2, c = i & 3;
            cp16(smem_u32(&sA[buf][r * SSTR + c * 8]),
                 Ap + (size_t)(m0 + r) * lda + k0 + c * 8, 16);
        }
        #pragma unroll
        for (int j = 0; j < 2; j++) {
            int i = tid + 256 * j;
            int r = i >> 2, c = i & 3;
            int gn = n0 + r;
            cp16(smem_u32(&sB[buf][r * SSTR + c * 8]),
                 Bp + (size_t)gn * ldb + k0 + c * 8, gn < N ? 16 : 0);
        }
        cp_commit();
    };

    auto compute_tile = [&](int buf) {
        #pragma unroll
        for (int s = 0; s < 2; s++) {
            const int kk = s * 16;
            uint32_t af[4][4], bf[4][2];
            #pragma unroll
            for (int mt = 0; mt < 4; mt++) {
                int rm = wm * 64 + mt * 16;
                const __nv_bfloat16* base = &sA[buf][(rm + gid) * SSTR + kk + 2 * tig];
                af[mt][0] = *(const uint32_t*)(base);
                af[mt][1] = *(const uint32_t*)(base + 8 * SSTR);
                af[mt][2] = *(const uint32_t*)(base + 8);
                af[mt][3] = *(const uint32_t*)(base + 8 * SSTR + 8);
            }
            #pragma unroll
            for (int nt = 0; nt < 4; nt++) {
                int cb = wn * 32 + nt * 8 + gid;
                const __nv_bfloat16* base = &sB[buf][cb * SSTR + kk + 2 * tig];
                bf[nt][0] = *(const uint32_t*)(base);
                bf[nt][1] = *(const uint32_t*)(base + 8);
            }
            #pragma unroll
            for (int mt = 0; mt < 4; mt++)
                #pragma unroll
                for (int nt = 0; nt < 4; nt++)
                    mma16(acc[mt][nt], af[mt], bf[nt]);
        }
    };

    load_tile(0, 0);
    for (int kt = 0; kt < kTiles; kt++) {
        if (kt + 1 < kTiles) {
            load_tile((kt + 1) & 1, kt + 1);
            cp_wait<1>();
        } else {
            cp_wait<0>();
        }
        __syncthreads();
        compute_tile(kt & 1);
        __syncthreads();
    }

    // epilogue
    #pragma unroll
    for (int mt = 0; mt < 4; mt++) {
        #pragma unroll
        for (int nt = 0; nt < 4; nt++) {
            int row0 = m0 + wm * 64 + mt * 16 + gid;
            int col0 = n0 + wn * 32 + nt * 8 + tig * 2;
            if (flags & 512) {
                float ba = bias[col0], bg = bias[col0 + 1];
                #pragma unroll
                for (int h = 0; h < 2; h++) {
                    int rr = row0 + h * 8;
                    float a = alpha * acc[mt][nt][2 * h] + ba;
                    float g = alpha * acc[mt][nt][2 * h + 1] + bg;
                    float gg = a * 0.5f * g * (1.f + erff(g * 0.70710678118654752f));
                    Cbp[(size_t)rr * ldcb + (col0 >> 1)] = __float2bfloat16(gg);
                }
                continue;
            }
            #pragma unroll
            for (int r = 0; r < 4; r++) {
                int rr = row0 + (r >> 1) * 8;
                int cc = col0 + (r & 1);
                if (cc >= N) continue;
                float vv = alpha * acc[mt][nt][r];
                size_t off = (size_t)rr * ldc + cc;
                if (flags & 4)   vv += bias[cc];
                if (flags & 256) vv += aux[(((size_t)(z >> 4)) * 1024 + rr) * ldaux + cc];
                if (flags & 1) vv += Cp[off];
                if (flags & 2) vv = fmaxf(vv, Cp[off]);
                if (!(flags & 32)) Cp[off] = vv;
                if (flags & 8)  Cbp[(size_t)rr * ldcb + cc] = __float2bfloat16(vv);
                if (flags & 16) Cbp[(size_t)cc * ldcb + rr] = __float2bfloat16(vv);
            }
        }
    }
}

static void gemm(const __nv_bfloat16* A, const __nv_bfloat16* B, const float* bias,
                 const float* aux, float* C, __nv_bfloat16* Cb,
                 int M, int N, int K, int lda, int ldb, int ldc, int ldcb, int ldaux,
                 long sA, long sB, long sC, long sCb, int bDiv, int batch,
                 float alpha, int flags)
{
    dim3 gr((N + 127) / 128, M / 128, batch);
    bgemm_k<<<gr, 256>>>(A, B, bias, aux, C, Cb, M, N, K,
                         lda, ldb, ldc, ldcb, ldaux,
                         sA, sB, sC, sCb, bDiv, alpha, flags);
}

// ---------------- LayerNorm (bf16 out) ----------------
__global__ void ln_k(const float* __restrict__ x, const float* __restrict__ w,
                     const float* __restrict__ b, __nv_bfloat16* __restrict__ y, int cols)
{
    int row = blockIdx.x;
    const float* xp = x + (size_t)row * cols;
    float s1 = 0.f, s2 = 0.f;
    for (int i = threadIdx.x; i < cols; i += blockDim.x) {
        float v = xp[i]; s1 += v; s2 += v * v;
    }
    __shared__ float r1[256], r2[256];
    r1[threadIdx.x] = s1; r2[threadIdx.x] = s2;
    __syncthreads();
    for (int s = 128; s > 0; s >>= 1) {
        if (threadIdx.x < s) { r1[threadIdx.x] += r1[threadIdx.x + s]; r2[threadIdx.x] += r2[threadIdx.x + s]; }
        __syncthreads();
    }
    float mean = r1[0] / cols;
    float var = r2[0] / cols - mean * mean;
    float rstd = rsqrtf(var + 1e-5f);
    __nv_bfloat16* yp = y + (size_t)row * cols;
    for (int i = threadIdx.x; i < cols; i += blockDim.x)
        yp[i] = __float2bfloat16((xp[i] - mean) * rstd * w[i] + b[i]);
}

// ---------------- softmax kv groups (256 cols, + agent_bias[m,nc2]) -> bf16 ----------------
__global__ void softmax_kv_k(const float* __restrict__ s, const float* __restrict__ abias,
                             __nv_bfloat16* __restrict__ ob)
{
    int gr = blockIdx.x;
    int c2 = blockIdx.y;
    int m = gr & 1023;
    const float* p = s + (size_t)gr * 512 + c2 * 256;
    __nv_bfloat16* po = ob + (size_t)gr * 512 + c2 * 256;
    int tid = threadIdx.x;
    float v = p[tid] + abias[(size_t)m * 256 + tid];
    __shared__ float red[256];
    red[tid] = v; __syncthreads();
    for (int st = 128; st; st >>= 1) { if (tid < st) red[tid] = fmaxf(red[tid], red[tid + st]); __syncthreads(); }
    float mx = red[0]; __syncthreads();
    float e = __expf(v - mx);
    red[tid] = e; __syncthreads();
    for (int st = 128; st; st >>= 1) { if (tid < st) red[tid] += red[tid + st]; __syncthreads(); }
    po[tid] = __float2bfloat16(e / red[0]);
}

// ---------------- softmax query rows (1024 cols, + query_bias[n,m]) -> bf16 ----------------
__global__ void softmax_aq_k(const float* __restrict__ s, const float* __restrict__ qbias,
                             __nv_bfloat16* __restrict__ ob)
{
    int gr = blockIdx.x;
    int n = gr & 1023;
    const float* p = s + (size_t)gr * 1024;
    __nv_bfloat16* po = ob + (size_t)gr * 1024;
    const float* bp = qbias + (size_t)n * 1024;
    int tid = threadIdx.x;
    float v[4];
    float mx = -1e30f;
    #pragma unroll
    for (int k = 0; k < 4; k++) { v[k] = p[tid + k * 256] + bp[tid + k * 256]; mx = fmaxf(mx, v[k]); }
    __shared__ float red[256];
    red[tid] = mx; __syncthreads();
    for (int st = 128; st; st >>= 1) { if (tid < st) red[tid] = fmaxf(red[tid], red[tid + st]); __syncthreads(); }
    mx = red[0]; __syncthreads();
    float sum = 0.f;
    #pragma unroll
    for (int k = 0; k < 4; k++) { v[k] = __expf(v[k] - mx); sum += v[k]; }
    red[tid] = sum; __syncthreads();
    for (int st = 128; st; st >>= 1) { if (tid < st) red[tid] += red[tid + st]; __syncthreads(); }
    float inv = 1.f / red[0];
    #pragma unroll
    for (int k = 0; k < 4; k++) po[tid + k * 256] = __float2bfloat16(v[k] * inv);
}

// ---------------- pose transpose -> bf16 ----------------
__global__ void poset_k(const float* __restrict__ pose, __nv_bfloat16* __restrict__ out)
{
    long idx = (long)blockIdx.x * blockDim.x + threadIdx.x;
    if (idx >= kHS) return;
    int d = (int)(idx % kQ);
    long r = idx / kQ;
    int n = (int)(r % kN); r /= kN;
    int t = (int)(r % kT); int b = (int)(r / kT);
    int h = n >> 5, w = n & 31;
    out[idx] = __float2bfloat16(pose[(((((size_t)b * kQ + d) * kT + t) * 32 + h) * 32) + w]);
}

// ---------------- context permuted rows -> bf16 ----------------
__global__ void ctxperm_k(const float* __restrict__ ctx, __nv_bfloat16* __restrict__ out)
{
    long idx = (long)blockIdx.x * blockDim.x + threadIdx.x;
    if (idx >= (long)kB * 512 * kCD) return;
    int k = (int)(idx % kCD);
    long r0 = idx / kCD;
    int r = (int)(r0 % 512); int b = (int)(r0 / 512);
    int n = ((r & 255) << 1) | (r >> 8);
    out[idx] = __float2bfloat16(ctx[(((size_t)b * kC + (n >> 8)) * kCtok + (n & 255)) * kCD + k]);
}

// ---------------- plain fp32->bf16 convert ----------------
__global__ void conv_k(const float* __restrict__ s, __nv_bfloat16* __restrict__ d, long n)
{
    long idx = (long)blockIdx.x * blockDim.x + threadIdx.x;
    if (idx < n) d[idx] = __float2bfloat16(s[idx]);
}

// ---------------- transpose convert: dst[b][c][r] = src[b][r][c] ----------------
__global__ void tconv_k(const float* __restrict__ s, __nv_bfloat16* __restrict__ d,
                        int R, int Cc, int batch)
{
    long n = (long)R * Cc * batch;
    long idx = (long)blockIdx.x * blockDim.x + threadIdx.x;
    if (idx >= n) return;
    int r = (int)(idx % R);
    long q = idx / R;
    int c = (int)(q % Cc);
    int b = (int)(q / Cc);
    d[idx] = __float2bfloat16(s[((size_t)b * R + r) * Cc + c]);
}

// ---------------- Wq natural, rows padded 320 -> 384 (pad rows = 0) ----------------
__global__ void wqpad_k(const float* __restrict__ s, __nv_bfloat16* __restrict__ d)
{
    long n = (long)2 * 384 * kI;
    long idx = (long)blockIdx.x * blockDim.x + threadIdx.x;
    if (idx >= n) return;
    int c = (int)(idx % kI);
    long q = idx / kI;
    int r = (int)(q % 384);
    int blk = (int)(q / 384);
    d[idx] = (r < kQ) ? __float2bfloat16(s[((size_t)blk * kQ + r) * kI + c])
                      : __float2bfloat16(0.f);
}

// ---------------- FF1 weight transpose with a/g column interleave ----------------
__global__ void w1i_k(const float* __restrict__ s, __nv_bfloat16* __restrict__ d)
{
    long n = (long)2 * kFF * kQ;
    long idx = (long)blockIdx.x * blockDim.x + threadIdx.x;
    if (idx >= n) return;
    int k = (int)(idx % kQ);
    int e = (int)(idx / kQ);
    int oc = (e & 1) ? (kFF + (e >> 1)) : (e >> 1);
    d[idx] = __float2bfloat16(s[(size_t)k * (2 * kFF) + oc]);
}
__global__ void b1i_k(const float* __restrict__ s, float* __restrict__ d)
{
    int e = blockIdx.x * blockDim.x + threadIdx.x;
    if (e >= 2 * kFF) return;
    int oc = (e & 1) ? (kFF + (e >> 1)) : (e >> 1);
    d[e] = s[oc];
}

// ---------------- depthwise 3x3 conv + frame max + bias ----------------
__global__ void dwconv_k(const float* __restrict__ v, const float* __restrict__ wgt,
                         const float* __restrict__ bias, float* __restrict__ out)
{
    int pix = blockIdx.x & 255;
    int b = blockIdx.x >> 8;
    int e = threadIdx.x;
    int h = pix >> 4, w = pix & 15;
    float wv[9];
    #pragma unroll
    for (int t9 = 0; t9 < 9; t9++) wv[t9] = wgt[e * 9 + t9];
    float best = -1e30f;
    #pragma unroll
    for (int c = 0; c < 2; c++) {
        float s = 0.f;
        #pragma unroll
        for (int dh = -1; dh <= 1; dh++)
            #pragma unroll
            for (int dw = -1; dw <= 1; dw++) {
                int hh = h + dh, ww = w + dw;
                if (hh < 0 || hh > 15 || ww < 0 || ww > 15) continue;
                s += v[((size_t)(b * kC + c) * kCtok + hh * 16 + ww) * kI + e] * wv[(dh + 1) * 3 + (dw + 1)];
            }
        best = fmaxf(best, s);
    }
    out[((size_t)b * kCtok + pix) * kI + e] = best + bias[e];
}

// ---------------- bilinear x2 upsample -> bf16 ----------------
__global__ void upsample_k(const float* __restrict__ vd, __nv_bfloat16* __restrict__ vtok)
{
    int opix = blockIdx.x & 1023;
    int b = blockIdx.x >> 10;
    int e = threadIdx.x;
    int y = opix >> 5, x = opix & 31;
    int py = y >> 1, px = x >> 1;
    int y0, y1, x0, x1; float wy0, wy1, wx0, wx1;
    if (y & 1) { y0 = py; y1 = min(py + 1, 15); wy0 = 0.75f; wy1 = 0.25f; }
    else       { y0 = max(py - 1, 0); y1 = py;  wy0 = 0.25f; wy1 = 0.75f; }
    if (x & 1) { x0 = px; x1 = min(px + 1, 15); wx0 = 0.75f; wx1 = 0.25f; }
    else       { x0 = max(px - 1, 0); x1 = px;  wx0 = 0.25f; wx1 = 0.75f; }
    const float* base = vd + (size_t)b * kCtok * kI;
    float r = wy0 * wx0 * base[(size_t)(y0 * 16 + x0) * kI + e]
            + wy0 * wx1 * base[(size_t)(y0 * 16 + x1) * kI + e]
            + wy1 * wx0 * base[(size_t)(y1 * 16 + x0) * kI + e]
            + wy1 * wx1 * base[(size_t)(y1 * 16 + x1) * kI + e];
    vtok[((size_t)b * kN + opix) * kI + e] = __float2bfloat16(r);
}

// ---------------- launch ----------------
extern "C" void kernel_launch(void* const* d_in, const int* in_sizes, int n_in,
                              void* d_out, int out_size)
{
    const float* hidden     = (const float*)d_in[0];
    const float* context    = (const float*)d_in[1];
    const float* pose       = (const float*)d_in[2];
    const float* Wq         = (const float*)d_in[3];
    const float* Wk         = (const float*)d_in[4];
    const float* Wv         = (const float*)d_in[5];
    const float* Wa         = (const float*)d_in[6];
    const float* agent_bias = (const float*)d_in[7];
    const float* query_bias = (const float*)d_in[8];
    const float* dwc_w      = (const float*)d_in[9];
    const float* dwc_b      = (const float*)d_in[10];
    const float* Wo         = (const float*)d_in[11];
    const float* norm_w     = (const float*)d_in[12];
    const float* norm_b     = (const float*)d_in[13];
    const float* ffln_w     = (const float*)d_in[14];
    const float* ffln_b     = (const float*)d_in[15];
    const float* ff_w1      = (const float*)d_in[16];
    const float* ff_b1      = (const float*)d_in[17];
    const float* ff_w2      = (const float*)d_in[18];
    const float* ff_b2      = (const float*)d_in[19];

    float *hs, *vP, *scoresP, *akvP, *vdP, *vtokWoP, *aqP, *ffb1iP;
    cudaGetSymbolAddress((void**)&hs, g_hs);
    cudaGetSymbolAddress((void**)&vP, g_v);
    cudaGetSymbolAddress((void**)&scoresP, g_scores);
    cudaGetSymbolAddress((void**)&akvP, g_akv);
    cudaGetSymbolAddress((void**)&vdP, g_vdmax);
    cudaGetSymbolAddress((void**)&vtokWoP, g_vtokWo);
    cudaGetSymbolAddress((void**)&aqP, g_aq);
    cudaGetSymbolAddress((void**)&ffb1iP, g_ffb1i);

    __nv_bfloat16 *posetB, *ctxpermB, *ctxB, *WkT, *WvT, *WaN, *WqP, *WoT, *fw1T, *fw2T,
                  *kPB, *vTB, *SB, *GTB, *UB, *scoresB, *akvB, *akvWoT, *aqB, *vtokB, *nhB, *ggB;
    cudaGetSymbolAddress((void**)&posetB, b_poset);
    cudaGetSymbolAddress((void**)&ctxpermB, b_ctxperm);
    cudaGetSymbolAddress((void**)&ctxB, b_ctx);
    cudaGetSymbolAddress((void**)&WkT, b_WkT);
    cudaGetSymbolAddress((void**)&WvT, b_WvT);
    cudaGetSymbolAddress((void**)&WaN, b_Wanat);
    cudaGetSymbolAddress((void**)&WqP, b_Wqpad);
    cudaGetSymbolAddress((void**)&WoT, b_WoT);
    cudaGetSymbolAddress((void**)&fw1T, b_ffw1T);
    cudaGetSymbolAddress((void**)&fw2T, b_ffw2T);
    cudaGetSymbolAddress((void**)&kPB, b_kP);
    cudaGetSymbolAddress((void**)&vTB, b_vT);
    cudaGetSymbolAddress((void**)&SB, b_S);
    cudaGetSymbolAddress((void**)&GTB, b_GT);
    cudaGetSymbolAddress((void**)&UB, b_U);
    cudaGetSymbolAddress((void**)&scoresB, b_scores);
    cudaGetSymbolAddress((void**)&akvB, b_akv);
    cudaGetSymbolAddress((void**)&akvWoT, b_akvWoT);
    cudaGetSymbolAddress((void**)&aqB, b_aq);
    cudaGetSymbolAddress((void**)&vtokB, b_vtok);
    cudaGetSymbolAddress((void**)&nhB, b_nh);
    cudaGetSymbolAddress((void**)&ggB, b_gg);

    const float SCALE = 0.125f;
    auto cdiv = [](long a, long b) { return (int)((a + b - 1) / b); };

    cudaMemcpyAsync(hs, hidden, sizeof(float) * kHS, cudaMemcpyDeviceToDevice, 0);
    poset_k<<<cdiv(kHS, 256), 256>>>(pose, posetB);
    ctxperm_k<<<cdiv((long)kB * 512 * kCD, 256), 256>>>(context, ctxpermB);
    conv_k<<<cdiv((long)kB * kC * kCtok * kCD, 256), 256>>>(context, ctxB, (long)kB * kC * kCtok * kCD);
    tconv_k<<<cdiv((long)2 * kCD * kI, 256), 256>>>(Wk, WkT, kCD, kI, 2);
    tconv_k<<<cdiv((long)2 * kCD * kI, 256), 256>>>(Wv, WvT, kCD, kI, 2);
    conv_k<<<cdiv((long)2 * kQ * kI, 256), 256>>>(Wa, WaN, (long)2 * kQ * kI);
    wqpad_k<<<cdiv((long)2 * 384 * kI, 256), 256>>>(Wq, WqP);
    tconv_k<<<cdiv((long)2 * kI * kQ, 256), 256>>>(Wo, WoT, kI, kQ, 2);
    w1i_k<<<cdiv((long)2 * kFF * kQ, 256), 256>>>(ff_w1, fw1T);
    b1i_k<<<cdiv(2 * kFF, 256), 256>>>(ff_b1, ffb1iP);
    tconv_k<<<cdiv((long)kFF * kQ, 256), 256>>>(ff_w2, fw2T, kFF, kQ, 1);

    for (int blk = 0; blk < 2; blk++) {
        const __nv_bfloat16* WkT_b = WkT + (size_t)blk * kI * kCD;
        const __nv_bfloat16* WvT_b = WvT + (size_t)blk * kI * kCD;
        const __nv_bfloat16* WaN_b = WaN + (size_t)blk * kQ * kI;
        const __nv_bfloat16* WqP_b = WqP + (size_t)blk * 384 * kI;
        const __nv_bfloat16* WoT_b = WoT + (size_t)blk * kQ * kI;
        __nv_bfloat16* GT_b = GTB + (size_t)blk * kQ * 384;
        const float* ab_b = agent_bias + (size_t)blk * kN * kCtok;
        const float* qb_b = query_bias + (size_t)blk * kN * kN;
        const float* dw_b = dwc_w + (size_t)blk * kI * 9;
        const float* db_b = dwc_b + (size_t)blk * kI;

        // kP (bf16 natural only): [b] 512x512, K=1024
        gemm(ctxpermB, WkT_b, nullptr, nullptr, nullptr, kPB,
             512, kI, kCD, kCD, kCD, 0, kI, 0,
             512L * kCD, 0, 0, 512L * kI, 1, kB, 1.f, 8 | 32);
        // S_b = kP @ Wa^T : per b, 512x320, K=512 (bf16 natural)
        gemm(kPB, WaN_b, nullptr, nullptr, nullptr, SB,
             512, kQ, kI, kI, kI, 0, kQ, 0,
             512L * kI, 0, 0, 512L * kQ, 1, kB, 1.f, 8 | 32);
        // G^T = (Wq_pad @ Wa^T)^T : 384x320 -> GT (320x384, bf16 transposed)
        gemm(WqP_b, WaN_b, nullptr, nullptr, nullptr, GT_b,
             384, kQ, kI, kI, kI, 0, 384, 0,
             0, 0, 0, 0, 1, 1, 1.f, 16 | 32);
        // v proj: fp32 natural + bf16 transposed; [b,c] 256x512, K=1024
        gemm(ctxB, WvT_b, nullptr, nullptr, vP, vTB,
             kCtok, kI, kCD, kCD, kCD, kI, kCtok, 0,
             (long)kCtok * kCD, 0, (long)kCtok * kI, (long)kI * kCtok, 1, kB * kC, 1.f, 16);
        // scores = SCALE * poset @ S_b^T : per (b,t) 1024x512, K=320
        gemm(posetB, SB, nullptr, nullptr, scoresP, nullptr,
             kN, 512, kQ, kQ, kQ, 512, 0, 0,
             (long)kN * kQ, 512L * kQ, (long)kN * 512, 0, kT, kB * kT, SCALE, 0);
        softmax_kv_k<<<dim3(kB * kT * kN, 2), 256>>>(scoresP, ab_b, scoresB);
        // agent_kv = max_c2(probs_c2 @ v_c2): per (b,t) 1024x512, K=256
        gemm(scoresB, vTB, nullptr, nullptr, akvP, nullptr,
             kN, kI, kCtok, 512, kCtok, kI, 0, 0,
             (long)kN * 512, (long)kC * kI * kCtok, (long)kN * kI, 0, kT, kB * kT, 1.f, 0);
        gemm(scoresB + 256, vTB + (size_t)kI * kCtok, nullptr, nullptr, akvP, akvB,
             kN, kI, kCtok, 512, kCtok, kI, kI, 0,
             (long)kN * 512, (long)kC * kI * kCtok, (long)kN * kI, (long)kN * kI, kT, kB * kT,
             1.f, 2 | 8 | 32);
        // akvWo^T (bf16 transposed): per (b,t) [1024x320] from akv[1024x512] @ Wo
        gemm(akvB, WoT_b, nullptr, nullptr, akvP, akvWoT,
             kN, kQ, kI, kI, kI, kQ, kN, 0,
             (long)kN * kI, 0, 0, (long)kQ * kN, 1, kB * kT, 1.f, 16 | 32);
        // dwconv + upsample (bf16 v_tok)
        dwconv_k<<<kB * kCtok, kI>>>(vP, dw_b, db_b, vdP);
        upsample_k<<<kB * kN, kI>>>(vdP, vtokB);
        // vtokWo = v_tok @ Wo : per b, 1024x320, K=512 (fp32)
        gemm(vtokB, WoT_b, nullptr, nullptr, vtokWoP, nullptr,
             kN, kQ, kI, kI, kI, kQ, 0, 0,
             (long)kN * kI, 0, (long)kN * kQ, 0, 1, kB, 1.f, 0);
        // LN
        ln_k<<<(int)kTOK, 256>>>(hs, norm_w, norm_b, nhB, kQ);
        // U = nh @ G^T : 32768x320, K=320 (bf16 natural)
        gemm(nhB, GT_b, nullptr, nullptr, nullptr, UB,
             (int)kTOK, kQ, kQ, kQ, 384, 0, kQ, 0,
             0, 0, 0, 0, 1, 1, 1.f, 8 | 32);
        // aq = SCALE * U @ poset^T : per (b,t) 1024x1024, K=320
        gemm(UB, posetB, nullptr, nullptr, aqP, nullptr,
             kN, kN, kQ, kQ, kQ, kN, 0, 0,
             (long)kN * kQ, (long)kN * kQ, (long)kN * kN, 0, 1, kB * kT, SCALE, 0);
        softmax_aq_k<<<(int)kTOK, 256>>>(aqP, qb_b, aqB);
        // hs += aq @ akvWo + vtokWo : per (b,t) 1024x320, K=1024
        gemm(aqB, akvWoT, nullptr, vtokWoP, hs, nullptr,
             kN, kQ, kN, kN, kN, kQ, 0, kQ,
             (long)kN * kN, (long)kQ * kN, (long)kN * kQ, 0, 1, kB * kT,
             1.f, 1 | 256);
    }

    // ---- FF: LN -> fused FF1+GEGLU -> FF2, residual ----
    ln_k<<<(int)kTOK, 256>>>(hs, ffln_w, ffln_b, nhB, kQ);
    gemm(nhB, fw1T, ffb1iP, nullptr, nullptr, ggB,
         (int)kTOK, 2 * kFF, kQ, kQ, kQ, 0, kFF, 0,
         0, 0, 0, 0, 1, 1, 1.f, 4 | 32 | 512);
    gemm(ggB, fw2T, ff_b2, nullptr, hs, nullptr,
         (int)kTOK, kQ, kFF, kFF, kFF, kQ, 0, 0,
         0, 0, 0, 0, 1, 1, 1.f, 1 | 4);

    cudaMemcpyAsync(d_out, hs, sizeof(float) * kHS, cudaMemcpyDeviceToDevice, 0);
}